// round 10
// baseline (speedup 1.0000x reference)
#include <cuda_runtime.h>
#include <cuda_bf16.h>
#include <math.h>
#include <stdint.h>

// Problem constants
#define NROWS 32768
#define DIM   2048
#define BLK   512
#define NX    (NROWS * DIM / BLK)   // 131072 rows of X
#define EPSV  1e-5f
#define NITER 5
#define NSCTAS 128

// ---------------- device scratch (no allocations allowed) ----------------
__device__ float g_meanAcc[BLK];
__device__ float g_mean[BLK];
__device__ float g_G[BLK * BLK];
__device__ float g_C[BLK * BLK];
__device__ float g_Y[2][BLK * BLK];
__device__ float g_Z[2][BLK * BLK];
__device__ float g_T[BLK * BLK];
__device__ float g_normSq;
__device__ float g_invNorm;
__device__ float g_zscale;
__device__ float g_Wf[DIM * DIM];      // folded weight fp32 (for bias)
__device__ float g_beff[DIM];
__device__ unsigned g_nsBar;           // NS global barrier counter (zeroed per launch)

// bf16 hi/lo splits
__device__ __nv_bfloat16 g_xh[(size_t)NROWS * DIM];   // x row-major hi
__device__ __nv_bfloat16 g_xl[(size_t)NROWS * DIM];   // x row-major lo
__device__ __nv_bfloat16 g_wh[(size_t)DIM * DIM];     // Wf hi
__device__ __nv_bfloat16 g_wl[(size_t)DIM * DIM];     // Wf lo
__device__ __nv_bfloat16 g_vh[(size_t)DIM * DIM];     // raw weight hi
__device__ __nv_bfloat16 g_vl[(size_t)DIM * DIM];     // raw weight lo
__device__ __nv_bfloat16 g_xth[(size_t)BLK * NX];     // X^T hi  [512][131072]
__device__ __nv_bfloat16 g_xtl[(size_t)BLK * NX];     // X^T lo
__device__ __nv_bfloat16 g_zth[BLK * BLK];            // Zfinal^T hi [512][512] (n-major)
__device__ __nv_bfloat16 g_ztl[BLK * BLK];            // Zfinal^T lo

// symmetric gram tile pairs (lower triangle, 10 of 16)
__constant__ int c_pa[10] = {0,1,1,2,2,2,3,3,3,3};
__constant__ int c_pb[10] = {0,0,1,0,1,2,0,1,2,3};

// ---------------- PTX helpers (sm_80+ features only) ----------------
__device__ __forceinline__ uint32_t smem_u32(const void* p) {
    uint32_t a;
    asm("{ .reg .u64 t; cvta.to.shared.u64 t, %1; cvt.u32.u64 %0, t; }" : "=r"(a) : "l"(p));
    return a;
}
__device__ __forceinline__ void cp16(uint32_t d, const void* s) {
    asm volatile("cp.async.cg.shared.global [%0], [%1], 16;" :: "r"(d), "l"(s));
}
__device__ __forceinline__ void cp_commit() { asm volatile("cp.async.commit_group;"); }
__device__ __forceinline__ void cp_wait0()  { asm volatile("cp.async.wait_group 0;"); }
__device__ __forceinline__ void cp_wait1()  { asm volatile("cp.async.wait_group 1;"); }

__device__ __forceinline__ void ldsm4(uint32_t& r0, uint32_t& r1, uint32_t& r2, uint32_t& r3, uint32_t a) {
    asm volatile("ldmatrix.sync.aligned.m8n8.x4.shared.b16 {%0,%1,%2,%3}, [%4];"
                 : "=r"(r0), "=r"(r1), "=r"(r2), "=r"(r3) : "r"(a));
}
__device__ __forceinline__ void ldsm2(uint32_t& r0, uint32_t& r1, uint32_t a) {
    asm volatile("ldmatrix.sync.aligned.m8n8.x2.shared.b16 {%0,%1}, [%2];"
                 : "=r"(r0), "=r"(r1) : "r"(a));
}
__device__ __forceinline__ void mma16816bf(float* c, const uint32_t* a, uint32_t b0, uint32_t b1) {
    asm volatile("mma.sync.aligned.m16n8k16.row.col.f32.bf16.bf16.f32 "
                 "{%0,%1,%2,%3}, {%4,%5,%6,%7}, {%8,%9}, {%0,%1,%2,%3};"
                 : "+f"(c[0]), "+f"(c[1]), "+f"(c[2]), "+f"(c[3])
                 : "r"(a[0]), "r"(a[1]), "r"(a[2]), "r"(a[3]), "r"(b0), "r"(b1));
}

// ---------------- zero accumulators ----------------
__global__ void zero_kernel() {
    int idx = blockIdx.x * blockDim.x + threadIdx.x;
    int total = BLK * BLK + BLK + 2;
    for (int i = idx; i < total; i += gridDim.x * blockDim.x) {
        if (i < BLK * BLK) g_G[i] = 0.0f;
        else if (i < BLK * BLK + BLK) g_meanAcc[i - BLK * BLK] = 0.0f;
        else if (i == BLK * BLK + BLK) g_normSq = 0.0f;
        else g_nsBar = 0u;
    }
}

// ---------------- merged x preprocessing ----------------
// view x as [131072][512]; per 64x64 tile: elementwise hi/lo (row-major),
// transposed hi/lo, and column partial sums.
__global__ void __launch_bounds__(256) xprep_kernel(const float* __restrict__ x) {
    __shared__ float tile[64][65];
    const int tid = threadIdx.x;
    const int r0 = blockIdx.x * 64;     // 2048 blocks over rows
    const int c0 = blockIdx.y * 64;     // 8 blocks over cols
    #pragma unroll
    for (int i = 0; i < 4; i++) {
        int r = i * 16 + (tid >> 4);
        int c = (tid & 15) * 4;
        size_t flat = (size_t)(r0 + r) * BLK + c0 + c;
        float4 v = *(const float4*)(x + flat);
        tile[r][c] = v.x; tile[r][c + 1] = v.y; tile[r][c + 2] = v.z; tile[r][c + 3] = v.w;
        // row-major elementwise split
        __nv_bfloat16 h0 = __float2bfloat16(v.x), h1 = __float2bfloat16(v.y);
        __nv_bfloat16 h2 = __float2bfloat16(v.z), h3 = __float2bfloat16(v.w);
        __nv_bfloat16 l0 = __float2bfloat16(v.x - __bfloat162float(h0));
        __nv_bfloat16 l1 = __float2bfloat16(v.y - __bfloat162float(h1));
        __nv_bfloat16 l2 = __float2bfloat16(v.z - __bfloat162float(h2));
        __nv_bfloat16 l3 = __float2bfloat16(v.w - __bfloat162float(h3));
        *(__nv_bfloat162*)(g_xh + flat)     = __halves2bfloat162(h0, h1);
        *(__nv_bfloat162*)(g_xh + flat + 2) = __halves2bfloat162(h2, h3);
        *(__nv_bfloat162*)(g_xl + flat)     = __halves2bfloat162(l0, l1);
        *(__nv_bfloat162*)(g_xl + flat + 2) = __halves2bfloat162(l2, l3);
    }
    __syncthreads();
    #pragma unroll
    for (int i = 0; i < 4; i++) {
        int cc = i * 16 + (tid >> 4);
        int r = (tid & 15) * 4;
        float v0 = tile[r][cc], v1 = tile[r + 1][cc], v2 = tile[r + 2][cc], v3 = tile[r + 3][cc];
        // transposed split
        __nv_bfloat16 h0 = __float2bfloat16(v0), h1 = __float2bfloat16(v1);
        __nv_bfloat16 h2 = __float2bfloat16(v2), h3 = __float2bfloat16(v3);
        __nv_bfloat16 l0 = __float2bfloat16(v0 - __bfloat162float(h0));
        __nv_bfloat16 l1 = __float2bfloat16(v1 - __bfloat162float(h1));
        __nv_bfloat16 l2 = __float2bfloat16(v2 - __bfloat162float(h2));
        __nv_bfloat16 l3 = __float2bfloat16(v3 - __bfloat162float(h3));
        size_t o = (size_t)(c0 + cc) * NX + r0 + r;
        *(__nv_bfloat162*)(g_xth + o)     = __halves2bfloat162(h0, h1);
        *(__nv_bfloat162*)(g_xth + o + 2) = __halves2bfloat162(h2, h3);
        *(__nv_bfloat162*)(g_xtl + o)     = __halves2bfloat162(l0, l1);
        *(__nv_bfloat162*)(g_xtl + o + 2) = __halves2bfloat162(l2, l3);
        // column partial sum: reduce the 16 threads that share cc
        float s = v0 + v1 + v2 + v3;
        #pragma unroll
        for (int off = 8; off > 0; off >>= 1)
            s += __shfl_down_sync(0xffffffffu, s, off, 16);
        if ((tid & 15) == 0) atomicAdd(&g_meanAcc[c0 + cc], s);
    }
}

__global__ void mean_scale_kernel() {
    int t = threadIdx.x;
    g_mean[t] = g_meanAcc[t] * (1.0f / (float)NX);
}

// ---------------- raw weight split ----------------
__global__ void split_v_kernel(const float* __restrict__ W) {
    size_t i = ((size_t)blockIdx.x * 256 + threadIdx.x) * 4;
    float4 v = *(const float4*)(W + i);
    __nv_bfloat16 h0 = __float2bfloat16(v.x), h1 = __float2bfloat16(v.y);
    __nv_bfloat16 h2 = __float2bfloat16(v.z), h3 = __float2bfloat16(v.w);
    __nv_bfloat16 l0 = __float2bfloat16(v.x - __bfloat162float(h0));
    __nv_bfloat16 l1 = __float2bfloat16(v.y - __bfloat162float(h1));
    __nv_bfloat16 l2 = __float2bfloat16(v.z - __bfloat162float(h2));
    __nv_bfloat16 l3 = __float2bfloat16(v.w - __bfloat162float(h3));
    *(__nv_bfloat162*)(g_vh + i)     = __halves2bfloat162(h0, h1);
    *(__nv_bfloat162*)(g_vh + i + 2) = __halves2bfloat162(h2, h3);
    *(__nv_bfloat162*)(g_vl + i)     = __halves2bfloat162(l0, l1);
    *(__nv_bfloat162*)(g_vl + i + 2) = __halves2bfloat162(l2, l3);
}

// ============ MMA tile machinery: BK=32, 64B rows, 4-chunk XOR swizzle ============
#define OSTG 32768

// ---------------- gram via mma bf16x3 ----------------
__device__ __forceinline__ void load_stage_gram(uint32_t sbase, int a0, int b0, int k0, int tid) {
    #pragma unroll
    for (int i = 0; i < 8; i++) {
        int q = tid + i * 256;
        int op = q >> 9, rem = q & 511;
        int r = rem >> 2, c = rem & 3;
        uint32_t dst = sbase + (uint32_t)op * 8192u + (uint32_t)(r * 64) + (uint32_t)((c ^ ((r >> 1) & 3)) * 16);
        const __nv_bfloat16* src;
        if (op == 0)      src = g_xth + (size_t)(a0 + r) * NX + k0 + c * 8;
        else if (op == 1) src = g_xtl + (size_t)(a0 + r) * NX + k0 + c * 8;
        else if (op == 2) src = g_xth + (size_t)(b0 + r) * NX + k0 + c * 8;
        else              src = g_xtl + (size_t)(b0 + r) * NX + k0 + c * 8;
        cp16(dst, src);
    }
}

__global__ void __launch_bounds__(256) gram_mma(int dummy) {
    extern __shared__ __align__(16) char dsm[];
    const uint32_t sb = smem_u32(dsm);
    const int tid = threadIdx.x, lane = tid & 31, wid = tid >> 5;
    const int a0 = c_pa[blockIdx.x] * 128;
    const int b0 = c_pb[blockIdx.x] * 128;
    const int kbase = blockIdx.y * 2048;
    const int wm = wid & 1, wn = wid >> 1;

    float c[4][4][4];
    #pragma unroll
    for (int mf = 0; mf < 4; mf++)
        #pragma unroll
        for (int nf = 0; nf < 4; nf++)
            #pragma unroll
            for (int r = 0; r < 4; r++) c[mf][nf][r] = 0.0f;

    load_stage_gram(sb,        a0, b0, kbase,      tid); cp_commit();
    load_stage_gram(sb + OSTG, a0, b0, kbase + 32, tid); cp_commit();

    const int a_row = wm * 64 + (lane & 15);
    const int a_kc  = (lane >> 4) & 1;
    const int b_row = wn * 32 + (lane & 7);
    const int b_kc  = (lane >> 3) & 1;

    int cs = 0, ls = 2;
    for (int it = 0; it < 64; it++) {
        cp_wait1();
        __syncthreads();
        int pf = it + 2; if (pf > 63) pf = 63;
        load_stage_gram(sb + (uint32_t)ls * OSTG, a0, b0, kbase + pf * 32, tid);
        cp_commit();
        const uint32_t sa = sb + (uint32_t)cs * OSTG;

        #pragma unroll
        for (int s = 0; s < 2; s++) {
            uint32_t ah[4][4], al[4][4];
            #pragma unroll
            for (int mf = 0; mf < 4; mf++) {
                int r = a_row + mf * 16;
                uint32_t addr = sa + (uint32_t)(r * 64) +
                                (uint32_t)((((s << 1) | a_kc) ^ ((r >> 1) & 3)) * 16);
                ldsm4(ah[mf][0], ah[mf][1], ah[mf][2], ah[mf][3], addr);
                ldsm4(al[mf][0], al[mf][1], al[mf][2], al[mf][3], addr + 8192u);
            }
            #pragma unroll
            for (int nf = 0; nf < 4; nf++) {
                int r = b_row + nf * 8;
                uint32_t base = (uint32_t)(r * 64) +
                                (uint32_t)((((s << 1) | b_kc) ^ ((r >> 1) & 3)) * 16);
                uint32_t bh0, bh1, bl0, bl1;
                ldsm2(bh0, bh1, sa + 16384u + base);
                ldsm2(bl0, bl1, sa + 24576u + base);
                #pragma unroll
                for (int mf = 0; mf < 4; mf++) {
                    mma16816bf(c[mf][nf], ah[mf], bh0, bh1);
                    mma16816bf(c[mf][nf], ah[mf], bl0, bl1);
                    mma16816bf(c[mf][nf], al[mf], bh0, bh1);
                }
            }
        }
        cs = (cs == 2) ? 0 : cs + 1;
        ls = (ls == 2) ? 0 : ls + 1;
    }
    cp_wait0();

    #pragma unroll
    for (int mf = 0; mf < 4; mf++) {
        int r0 = a0 + wm * 64 + mf * 16 + (lane >> 2);
        #pragma unroll
        for (int nf = 0; nf < 4; nf++) {
            int cb = b0 + wn * 32 + nf * 8 + (lane & 3) * 2;
            atomicAdd(&g_G[r0 * BLK + cb],           c[mf][nf][0]);
            atomicAdd(&g_G[r0 * BLK + cb + 1],       c[mf][nf][1]);
            atomicAdd(&g_G[(r0 + 8) * BLK + cb],     c[mf][nf][2]);
            atomicAdd(&g_G[(r0 + 8) * BLK + cb + 1], c[mf][nf][3]);
        }
    }
}

// ---------------- cov = G/n - m m^T + eps I (mirror upper from lower) ----------------
__global__ void cov_kernel() {
    int idx = blockIdx.x * blockDim.x + threadIdx.x;
    int a = idx >> 9, b = idx & 511;
    float graw = (a >= b) ? g_G[a * BLK + b] : g_G[b * BLK + a];
    float c = graw * (1.0f / (float)NX) - g_mean[a] * g_mean[b] + (a == b ? EPSV : 0.0f);
    g_C[idx] = c;
    float v = c * c;
    #pragma unroll
    for (int o = 16; o > 0; o >>= 1) v += __shfl_xor_sync(0xffffffffu, v, o);
    __shared__ float ws[8];
    int lane = threadIdx.x & 31, w = threadIdx.x >> 5;
    if (lane == 0) ws[w] = v;
    __syncthreads();
    if (w == 0) {
        float t = (lane < 8) ? ws[lane] : 0.0f;
        #pragma unroll
        for (int o = 4; o > 0; o >>= 1) t += __shfl_xor_sync(0xffffffffu, t, o);
        if (lane == 0) atomicAdd(&g_normSq, t);
    }
}

__global__ void scalars_kernel() {
    float norm = sqrtf(g_normSq);
    g_invNorm = 1.0f / norm;
    g_zscale = rsqrtf(norm);
}

// ---------------- 512x512x512 GEMM core (SIMT, 64x64 tile) ----------------
__device__ __forceinline__ void mm512_tile(const float* __restrict__ A,
                                           const float* __restrict__ B,
                                           int m0, int n0, float acc[4][4]) {
    __shared__ float As[16][68];
    __shared__ float Bs[16][68];
    const int tid = threadIdx.x;
    const int tx = tid & 15, ty = tid >> 4;
    for (int k0 = 0; k0 < 512; k0 += 16) {
        #pragma unroll
        for (int i = 0; i < 4; i++) {
            int l = tid + i * 256;
            int m = l >> 4, k = l & 15;
            As[k][m] = A[(m0 + m) * 512 + k0 + k];
            int kb = l >> 6, n = l & 63;
            Bs[kb][n] = B[(k0 + kb) * 512 + n0 + n];
        }
        __syncthreads();
        #pragma unroll
        for (int k = 0; k < 16; k++) {
            float a[4], b[4];
            *(float4*)a = *(const float4*)&As[k][ty * 4];
            *(float4*)b = *(const float4*)&Bs[k][tx * 4];
            #pragma unroll
            for (int i = 0; i < 4; i++)
                #pragma unroll
                for (int j = 0; j < 4; j++) acc[i][j] += a[i] * b[j];
        }
        __syncthreads();
    }
}

// ---------------- persistent Newton-Schulz kernel ----------------
__device__ __forceinline__ void ns_gsync(int target) {
    __threadfence();                      // release writes + CCTL.IVALL (L1 invalidate)
    __syncthreads();
    if (threadIdx.x == 0) {
        atomicAdd(&g_nsBar, 1u);
        while (*((volatile unsigned*)&g_nsBar) < (unsigned)target) { }
    }
    __syncthreads();
}

__global__ void __launch_bounds__(256) ns_kernel() {
    const int b = blockIdx.x, tid = threadIdx.x;
    int syncNo = 0;

    // init Y0 = C/norm, Z0 = I
    float inv = g_invNorm;
    for (int i = b * 256 + tid; i < BLK * BLK; i += NSCTAS * 256) {
        g_Y[0][i] = g_C[i] * inv;
        g_Z[0][i] = ((i >> 9) == (i & 511)) ? 1.0f : 0.0f;
    }
    ns_gsync(++syncNo * NSCTAS);

    int cur = 0;
    for (int it = 0; it < NITER; it++) {
        if (b < 64) {   // T = 1.5 I - 0.5 (Z @ Y), tile b
            int m0 = (b >> 3) * 64, n0 = (b & 7) * 64;
            float acc[4][4] = {};
            mm512_tile(g_Z[cur], g_Y[cur], m0, n0, acc);
            int tx = tid & 15, ty = tid >> 4;
            #pragma unroll
            for (int i = 0; i < 4; i++)
                #pragma unroll
                for (int j = 0; j < 4; j++) {
                    int r = m0 + ty * 4 + i, c = n0 + tx * 4 + j;
                    g_T[r * 512 + c] = (r == c ? 1.5f : 0.0f) - 0.5f * acc[i][j];
                }
        }
        ns_gsync(++syncNo * NSCTAS);
        {   // P phase: CTAs 0-63 -> Ynew = Y@T; CTAs 64-127 -> Znew = T@Z
            int bb = (b < 64) ? b : b - 64;
            int m0 = (bb >> 3) * 64, n0 = (bb & 7) * 64;
            const float* A = (b < 64) ? g_Y[cur] : g_T;
            const float* B = (b < 64) ? g_T : g_Z[cur];
            float* C = (b < 64) ? g_Y[cur ^ 1] : g_Z[cur ^ 1];
            float acc[4][4] = {};
            mm512_tile(A, B, m0, n0, acc);
            int tx = tid & 15, ty = tid >> 4;
            #pragma unroll
            for (int i = 0; i < 4; i++)
                #pragma unroll
                for (int j = 0; j < 4; j++)
                    C[(m0 + ty * 4 + i) * 512 + n0 + tx * 4 + j] = acc[i][j];
        }
        ns_gsync(++syncNo * NSCTAS);
        cur ^= 1;
    }

    // transpose-split Zfinal: zth[n][k] = hi(Z[k][n])
    const float* Zf = g_Z[cur];
    for (int i = b * 256 + tid; i < BLK * BLK; i += NSCTAS * 256) {
        int n = i >> 9, k = i & 511;
        float v = Zf[k * 512 + n];
        __nv_bfloat16 h = __float2bfloat16(v);
        g_zth[i] = h;
        g_ztl[i] = __float2bfloat16(v - __bfloat162float(h));
    }
}

// ---------------- fold via mma bf16x3: Wf = (W8192x512 @ Zf) * zscale ----------------
__device__ __forceinline__ void load_stage_fold(uint32_t sbase, int m0, int n0, int k0, int tid) {
    #pragma unroll
    for (int i = 0; i < 8; i++) {
        int q = tid + i * 256;
        int op = q >> 9, rem = q & 511;
        int r = rem >> 2, c = rem & 3;
        uint32_t dst = sbase + (uint32_t)op * 8192u + (uint32_t)(r * 64) + (uint32_t)((c ^ ((r >> 1) & 3)) * 16);
        const __nv_bfloat16* src;
        if (op == 0)      src = g_vh  + (size_t)(m0 + r) * 512 + k0 + c * 8;
        else if (op == 1) src = g_vl  + (size_t)(m0 + r) * 512 + k0 + c * 8;
        else if (op == 2) src = g_zth + (size_t)(n0 + r) * 512 + k0 + c * 8;
        else              src = g_ztl + (size_t)(n0 + r) * 512 + k0 + c * 8;
        cp16(dst, src);
    }
}

__global__ void __launch_bounds__(256) fold_mma(int dummy) {
    extern __shared__ __align__(16) char dsm[];
    const uint32_t sb = smem_u32(dsm);
    const int tid = threadIdx.x, lane = tid & 31, wid = tid >> 5;
    const int n0 = blockIdx.x * 128;   // N = 512 -> 4
    const int m0 = blockIdx.y * 128;   // M = 8192 -> 64
    const int wm = wid & 1, wn = wid >> 1;

    float c[4][4][4];
    #pragma unroll
    for (int mf = 0; mf < 4; mf++)
        #pragma unroll
        for (int nf = 0; nf < 4; nf++)
            #pragma unroll
            for (int r = 0; r < 4; r++) c[mf][nf][r] = 0.0f;

    load_stage_fold(sb,        m0, n0, 0,  tid); cp_commit();
    load_stage_fold(sb + OSTG, m0, n0, 32, tid); cp_commit();

    const int a_row = wm * 64 + (lane & 15);
    const int a_kc  = (lane >> 4) & 1;
    const int b_row = wn * 32 + (lane & 7);
    const int b_kc  = (lane >> 3) & 1;

    int cs = 0, ls = 2;
    for (int it = 0; it < 16; it++) {            // K = 512, BK = 32
        cp_wait1();
        __syncthreads();
        int pf = it + 2; if (pf > 15) pf = 15;
        load_stage_fold(sb + (uint32_t)ls * OSTG, m0, n0, pf * 32, tid);
        cp_commit();
        const uint32_t sa = sb + (uint32_t)cs * OSTG;

        #pragma unroll
        for (int s = 0; s < 2; s++) {
            uint32_t ah[4][4], al[4][4];
            #pragma unroll
            for (int mf = 0; mf < 4; mf++) {
                int r = a_row + mf * 16;
                uint32_t addr = sa + (uint32_t)(r * 64) +
                                (uint32_t)((((s << 1) | a_kc) ^ ((r >> 1) & 3)) * 16);
                ldsm4(ah[mf][0], ah[mf][1], ah[mf][2], ah[mf][3], addr);
                ldsm4(al[mf][0], al[mf][1], al[mf][2], al[mf][3], addr + 8192u);
            }
            #pragma unroll
            for (int nf = 0; nf < 4; nf++) {
                int r = b_row + nf * 8;
                uint32_t base = (uint32_t)(r * 64) +
                                (uint32_t)((((s << 1) | b_kc) ^ ((r >> 1) & 3)) * 16);
                uint32_t bh0, bh1, bl0, bl1;
                ldsm2(bh0, bh1, sa + 16384u + base);
                ldsm2(bl0, bl1, sa + 24576u + base);
                #pragma unroll
                for (int mf = 0; mf < 4; mf++) {
                    mma16816bf(c[mf][nf], ah[mf], bh0, bh1);
                    mma16816bf(c[mf][nf], ah[mf], bl0, bl1);
                    mma16816bf(c[mf][nf], al[mf], bh0, bh1);
                }
            }
        }
        cs = (cs == 2) ? 0 : cs + 1;
        ls = (ls == 2) ? 0 : ls + 1;
    }
    cp_wait0();

    // epilogue: scale, write fp32 Wf AND bf16 hi/lo split
    float sc = g_zscale;
    #pragma unroll
    for (int mf = 0; mf < 4; mf++) {
        int r0 = m0 + wm * 64 + mf * 16 + (lane >> 2);
        #pragma unroll
        for (int nf = 0; nf < 4; nf++) {
            int cb = n0 + wn * 32 + nf * 8 + (lane & 3) * 2;
            #pragma unroll
            for (int half = 0; half < 2; half++) {
                int row = r0 + half * 8;
                float w0 = c[mf][nf][half * 2 + 0] * sc;
                float w1 = c[mf][nf][half * 2 + 1] * sc;
                size_t idx = (size_t)row * 512 + cb;
                *(float2*)&g_Wf[idx] = make_float2(w0, w1);
                __nv_bfloat16 h0 = __float2bfloat16(w0), h1 = __float2bfloat16(w1);
                __nv_bfloat16 l0 = __float2bfloat16(w0 - __bfloat162float(h0));
                __nv_bfloat16 l1 = __float2bfloat16(w1 - __bfloat162float(h1));
                *(__nv_bfloat162*)(g_wh + idx) = __halves2bfloat162(h0, h1);
                *(__nv_bfloat162*)(g_wl + idx) = __halves2bfloat162(l0, l1);
            }
        }
    }
}

// ---------------- b_eff ----------------
__global__ void bias_kernel(const float* __restrict__ bias) {
    int o = blockIdx.x;
    int t = threadIdx.x;
    float s = 0.0f;
    for (int k = t; k < DIM; k += 256)
        s += g_Wf[o * DIM + k] * g_mean[k & 511];
    #pragma unroll
    for (int off = 16; off > 0; off >>= 1) s += __shfl_xor_sync(0xffffffffu, s, off);
    __shared__ float ws[8];
    int lane = t & 31, w = t >> 5;
    if (lane == 0) ws[w] = s;
    __syncthreads();
    if (t == 0) {
        float tot = 0.0f;
        #pragma unroll
        for (int i = 0; i < 8; i++) tot += ws[i];
        g_beff[o] = bias[o] - tot;
    }
}

// ---------------- main GEMM via mma bf16x3 (3-stage, BK=32) ----------------
__device__ __forceinline__ void load_stage_out(uint32_t sbase, int m0, int n0, int k0, int tid) {
    #pragma unroll
    for (int i = 0; i < 8; i++) {
        int q = tid + i * 256;
        int op = q >> 9, rem = q & 511;
        int r = rem >> 2, c = rem & 3;
        uint32_t dst = sbase + (uint32_t)op * 8192u + (uint32_t)(r * 64) + (uint32_t)((c ^ ((r >> 1) & 3)) * 16);
        const __nv_bfloat16* src;
        if (op == 0)      src = g_xh + (size_t)(m0 + r) * DIM + k0 + c * 8;
        else if (op == 1) src = g_xl + (size_t)(m0 + r) * DIM + k0 + c * 8;
        else if (op == 2) src = g_wh + (size_t)(n0 + r) * DIM + k0 + c * 8;
        else              src = g_wl + (size_t)(n0 + r) * DIM + k0 + c * 8;
        cp16(dst, src);
    }
}

__global__ void __launch_bounds__(256) out_gemm_mma(float* __restrict__ out) {
    extern __shared__ __align__(16) char dsm[];
    const uint32_t sb = smem_u32(dsm);
    float* sbias = (float*)(dsm + 3 * OSTG);
    const int tid = threadIdx.x, lane = tid & 31, wid = tid >> 5;
    const int n0 = blockIdx.x * 128, m0 = blockIdx.y * 128;
    const int wm = wid & 1, wn = wid >> 1;

    if (tid < 128) sbias[tid] = g_beff[n0 + tid];

    float c[4][4][4];
    #pragma unroll
    for (int mf = 0; mf < 4; mf++)
        #pragma unroll
        for (int nf = 0; nf < 4; nf++)
            #pragma unroll
            for (int r = 0; r < 4; r++) c[mf][nf][r] = 0.0f;

    load_stage_out(sb,        m0, n0, 0,  tid); cp_commit();
    load_stage_out(sb + OSTG, m0, n0, 32, tid); cp_commit();

    const int a_row = wm * 64 + (lane & 15);
    const int a_kc  = (lane >> 4) & 1;
    const int b_row = wn * 32 + (lane & 7);
    const int b_kc  = (lane >> 3) & 1;

    int cs = 0, ls = 2;
    for (int it = 0; it < 64; it++) {
        cp_wait1();
        __syncthreads();
        int pf = it + 2; if (pf > 63) pf = 63;
        load_stage_out(sb + (uint32_t)ls * OSTG, m0, n0, pf * 32, tid);
        cp_commit();
        const uint32_t sa = sb + (uint32_t)cs * OSTG;

        #pragma unroll
        for (int s = 0; s < 2; s++) {
            uint32_t ah[4][4], al[4][4];
            #pragma unroll
            for (int mf = 0; mf < 4; mf++) {
                int r = a_row + mf * 16;
                uint32_t addr = sa + (uint32_t)(r * 64) +
                                (uint32_t)((((s << 1) | a_kc) ^ ((r >> 1) & 3)) * 16);
                ldsm4(ah[mf][0], ah[mf][1], ah[mf][2], ah[mf][3], addr);
                ldsm4(al[mf][0], al[mf][1], al[mf][2], al[mf][3], addr + 8192u);
            }
            #pragma unroll
            for (int nf = 0; nf < 4; nf++) {
                int r = b_row + nf * 8;
                uint32_t base = (uint32_t)(r * 64) +
                                (uint32_t)((((s << 1) | b_kc) ^ ((r >> 1) & 3)) * 16);
                uint32_t bh0, bh1, bl0, bl1;
                ldsm2(bh0, bh1, sa + 16384u + base);
                ldsm2(bl0, bl1, sa + 24576u + base);
                #pragma unroll
                for (int mf = 0; mf < 4; mf++) {
                    mma16816bf(c[mf][nf], ah[mf], bh0, bh1);
                    mma16816bf(c[mf][nf], ah[mf], bl0, bl1);
                    mma16816bf(c[mf][nf], al[mf], bh0, bh1);
                }
            }
        }
        cs = (cs == 2) ? 0 : cs + 1;
        ls = (ls == 2) ? 0 : ls + 1;
    }
    cp_wait0();

    #pragma unroll
    for (int mf = 0; mf < 4; mf++) {
        int r0 = m0 + wm * 64 + mf * 16 + (lane >> 2);
        #pragma unroll
        for (int nf = 0; nf < 4; nf++) {
            int cb = wn * 32 + nf * 8 + (lane & 3) * 2;
            float2 v0, v1;
            v0.x = c[mf][nf][0] + sbias[cb];
            v0.y = c[mf][nf][1] + sbias[cb + 1];
            v1.x = c[mf][nf][2] + sbias[cb];
            v1.y = c[mf][nf][3] + sbias[cb + 1];
            *(float2*)&out[(size_t)r0 * DIM + n0 + cb] = v0;
            *(float2*)&out[(size_t)(r0 + 8) * DIM + n0 + cb] = v1;
        }
    }
}

// ---------------- host orchestration ----------------
extern "C" void kernel_launch(void* const* d_in, const int* in_sizes, int n_in,
                              void* d_out, int out_size) {
    const float* x      = (const float*)d_in[0];
    const float* weight = (const float*)d_in[1];
    const float* bias   = (const float*)d_in[2];
    float* out          = (float*)d_out;

    cudaFuncSetAttribute(gram_mma,     cudaFuncAttributeMaxDynamicSharedMemorySize, 3 * OSTG);
    cudaFuncSetAttribute(fold_mma,     cudaFuncAttributeMaxDynamicSharedMemorySize, 3 * OSTG);
    cudaFuncSetAttribute(out_gemm_mma, cudaFuncAttributeMaxDynamicSharedMemorySize, 3 * OSTG + 512);

    zero_kernel<<<1026, 256>>>();
    xprep_kernel<<<dim3(2048, 8), 256>>>(x);
    mean_scale_kernel<<<1, 512>>>();
    split_v_kernel<<<4096, 256>>>(weight);
    gram_mma<<<dim3(10, 64), 256, 3 * OSTG>>>(0);
    cov_kernel<<<1024, 256>>>();
    scalars_kernel<<<1, 1>>>();
    ns_kernel<<<NSCTAS, 256>>>();
    fold_mma<<<dim3(4, 64), 256, 3 * OSTG>>>(0);
    bias_kernel<<<DIM, 256>>>(bias);
    out_gemm_mma<<<dim3(16, 256), 256, 3 * OSTG + 512>>>(out);
}

// round 11
// speedup vs baseline: 1.0106x; 1.0106x over previous
#include <cuda_runtime.h>
#include <cuda_bf16.h>
#include <math.h>
#include <stdint.h>

// Problem constants
#define NROWS 32768
#define DIM   2048
#define BLK   512
#define NX    (NROWS * DIM / BLK)   // 131072 rows of X
#define EPSV  1e-5f
#define NITER 5

// ---------------- device scratch (no allocations allowed) ----------------
__device__ float g_meanAcc[BLK];
__device__ float g_mean[BLK];
__device__ float g_G[BLK * BLK];
__device__ float g_C[BLK * BLK];
__device__ float g_Y[2][BLK * BLK];
__device__ float g_Z[2][BLK * BLK];
__device__ float g_T[BLK * BLK];
__device__ float g_normSq;
__device__ float g_invNorm;
__device__ float g_zscale;
__device__ float g_Wf[DIM * DIM];      // folded weight fp32 (for bias)
__device__ float g_beff[DIM];

// bf16 hi/lo splits
__device__ __nv_bfloat16 g_xh[(size_t)NROWS * DIM];   // x row-major hi
__device__ __nv_bfloat16 g_xl[(size_t)NROWS * DIM];   // x row-major lo
__device__ __nv_bfloat16 g_wh[(size_t)DIM * DIM];     // Wf hi
__device__ __nv_bfloat16 g_wl[(size_t)DIM * DIM];     // Wf lo
__device__ __nv_bfloat16 g_vh[(size_t)DIM * DIM];     // raw weight hi
__device__ __nv_bfloat16 g_vl[(size_t)DIM * DIM];     // raw weight lo
__device__ __nv_bfloat16 g_xth[(size_t)BLK * NX];     // X^T hi  [512][131072]
__device__ __nv_bfloat16 g_xtl[(size_t)BLK * NX];     // X^T lo
__device__ __nv_bfloat16 g_zth[BLK * BLK];            // Zfinal^T hi [512][512] (n-major)
__device__ __nv_bfloat16 g_ztl[BLK * BLK];            // Zfinal^T lo

// symmetric gram tile pairs (lower triangle, 10 of 16)
__constant__ int c_pa[10] = {0,1,1,2,2,2,3,3,3,3};
__constant__ int c_pb[10] = {0,0,1,0,1,2,0,1,2,3};

// ---------------- PTX helpers (sm_80+ features only) ----------------
__device__ __forceinline__ uint32_t smem_u32(const void* p) {
    uint32_t a;
    asm("{ .reg .u64 t; cvta.to.shared.u64 t, %1; cvt.u32.u64 %0, t; }" : "=r"(a) : "l"(p));
    return a;
}
__device__ __forceinline__ void cp16(uint32_t d, const void* s) {
    asm volatile("cp.async.cg.shared.global [%0], [%1], 16;" :: "r"(d), "l"(s));
}
__device__ __forceinline__ void cp_commit() { asm volatile("cp.async.commit_group;"); }
__device__ __forceinline__ void cp_wait0()  { asm volatile("cp.async.wait_group 0;"); }
__device__ __forceinline__ void cp_wait1()  { asm volatile("cp.async.wait_group 1;"); }

__device__ __forceinline__ void ldsm4(uint32_t& r0, uint32_t& r1, uint32_t& r2, uint32_t& r3, uint32_t a) {
    asm volatile("ldmatrix.sync.aligned.m8n8.x4.shared.b16 {%0,%1,%2,%3}, [%4];"
                 : "=r"(r0), "=r"(r1), "=r"(r2), "=r"(r3) : "r"(a));
}
__device__ __forceinline__ void ldsm2(uint32_t& r0, uint32_t& r1, uint32_t a) {
    asm volatile("ldmatrix.sync.aligned.m8n8.x2.shared.b16 {%0,%1}, [%2];"
                 : "=r"(r0), "=r"(r1) : "r"(a));
}
__device__ __forceinline__ void mma16816bf(float* c, const uint32_t* a, uint32_t b0, uint32_t b1) {
    asm volatile("mma.sync.aligned.m16n8k16.row.col.f32.bf16.bf16.f32 "
                 "{%0,%1,%2,%3}, {%4,%5,%6,%7}, {%8,%9}, {%0,%1,%2,%3};"
                 : "+f"(c[0]), "+f"(c[1]), "+f"(c[2]), "+f"(c[3])
                 : "r"(a[0]), "r"(a[1]), "r"(a[2]), "r"(a[3]), "r"(b0), "r"(b1));
}

// ---------------- zero accumulators ----------------
__global__ void zero_kernel() {
    int idx = blockIdx.x * blockDim.x + threadIdx.x;
    int total = BLK * BLK + BLK + 1;
    for (int i = idx; i < total; i += gridDim.x * blockDim.x) {
        if (i < BLK * BLK) g_G[i] = 0.0f;
        else if (i < BLK * BLK + BLK) g_meanAcc[i - BLK * BLK] = 0.0f;
        else g_normSq = 0.0f;
    }
}

// ---------------- merged x preprocessing ----------------
__global__ void __launch_bounds__(256) xprep_kernel(const float* __restrict__ x) {
    __shared__ float tile[64][65];
    const int tid = threadIdx.x;
    const int r0 = blockIdx.x * 64;     // 2048 blocks over rows
    const int c0 = blockIdx.y * 64;     // 8 blocks over cols
    #pragma unroll
    for (int i = 0; i < 4; i++) {
        int r = i * 16 + (tid >> 4);
        int c = (tid & 15) * 4;
        size_t flat = (size_t)(r0 + r) * BLK + c0 + c;
        float4 v = *(const float4*)(x + flat);
        tile[r][c] = v.x; tile[r][c + 1] = v.y; tile[r][c + 2] = v.z; tile[r][c + 3] = v.w;
        __nv_bfloat16 h0 = __float2bfloat16(v.x), h1 = __float2bfloat16(v.y);
        __nv_bfloat16 h2 = __float2bfloat16(v.z), h3 = __float2bfloat16(v.w);
        __nv_bfloat16 l0 = __float2bfloat16(v.x - __bfloat162float(h0));
        __nv_bfloat16 l1 = __float2bfloat16(v.y - __bfloat162float(h1));
        __nv_bfloat16 l2 = __float2bfloat16(v.z - __bfloat162float(h2));
        __nv_bfloat16 l3 = __float2bfloat16(v.w - __bfloat162float(h3));
        *(__nv_bfloat162*)(g_xh + flat)     = __halves2bfloat162(h0, h1);
        *(__nv_bfloat162*)(g_xh + flat + 2) = __halves2bfloat162(h2, h3);
        *(__nv_bfloat162*)(g_xl + flat)     = __halves2bfloat162(l0, l1);
        *(__nv_bfloat162*)(g_xl + flat + 2) = __halves2bfloat162(l2, l3);
    }
    __syncthreads();
    #pragma unroll
    for (int i = 0; i < 4; i++) {
        int cc = i * 16 + (tid >> 4);
        int r = (tid & 15) * 4;
        float v0 = tile[r][cc], v1 = tile[r + 1][cc], v2 = tile[r + 2][cc], v3 = tile[r + 3][cc];
        __nv_bfloat16 h0 = __float2bfloat16(v0), h1 = __float2bfloat16(v1);
        __nv_bfloat16 h2 = __float2bfloat16(v2), h3 = __float2bfloat16(v3);
        __nv_bfloat16 l0 = __float2bfloat16(v0 - __bfloat162float(h0));
        __nv_bfloat16 l1 = __float2bfloat16(v1 - __bfloat162float(h1));
        __nv_bfloat16 l2 = __float2bfloat16(v2 - __bfloat162float(h2));
        __nv_bfloat16 l3 = __float2bfloat16(v3 - __bfloat162float(h3));
        size_t o = (size_t)(c0 + cc) * NX + r0 + r;
        *(__nv_bfloat162*)(g_xth + o)     = __halves2bfloat162(h0, h1);
        *(__nv_bfloat162*)(g_xth + o + 2) = __halves2bfloat162(h2, h3);
        *(__nv_bfloat162*)(g_xtl + o)     = __halves2bfloat162(l0, l1);
        *(__nv_bfloat162*)(g_xtl + o + 2) = __halves2bfloat162(l2, l3);
        float s = v0 + v1 + v2 + v3;
        #pragma unroll
        for (int off = 8; off > 0; off >>= 1)
            s += __shfl_down_sync(0xffffffffu, s, off, 16);
        if ((tid & 15) == 0) atomicAdd(&g_meanAcc[c0 + cc], s);
    }
}

__global__ void mean_scale_kernel() {
    int t = threadIdx.x;
    g_mean[t] = g_meanAcc[t] * (1.0f / (float)NX);
}

// ---------------- raw weight split ----------------
__global__ void split_v_kernel(const float* __restrict__ W) {
    size_t i = ((size_t)blockIdx.x * 256 + threadIdx.x) * 4;
    float4 v = *(const float4*)(W + i);
    __nv_bfloat16 h0 = __float2bfloat16(v.x), h1 = __float2bfloat16(v.y);
    __nv_bfloat16 h2 = __float2bfloat16(v.z), h3 = __float2bfloat16(v.w);
    __nv_bfloat16 l0 = __float2bfloat16(v.x - __bfloat162float(h0));
    __nv_bfloat16 l1 = __float2bfloat16(v.y - __bfloat162float(h1));
    __nv_bfloat16 l2 = __float2bfloat16(v.z - __bfloat162float(h2));
    __nv_bfloat16 l3 = __float2bfloat16(v.w - __bfloat162float(h3));
    *(__nv_bfloat162*)(g_vh + i)     = __halves2bfloat162(h0, h1);
    *(__nv_bfloat162*)(g_vh + i + 2) = __halves2bfloat162(h2, h3);
    *(__nv_bfloat162*)(g_vl + i)     = __halves2bfloat162(l0, l1);
    *(__nv_bfloat162*)(g_vl + i + 2) = __halves2bfloat162(l2, l3);
}

// ============ MMA tile machinery: BK=32, 64B rows, 4-chunk XOR swizzle ============
#define OSTG 32768

// ---------------- gram via mma bf16x3 ----------------
__device__ __forceinline__ void load_stage_gram(uint32_t sbase, int a0, int b0, int k0, int tid) {
    #pragma unroll
    for (int i = 0; i < 8; i++) {
        int q = tid + i * 256;
        int op = q >> 9, rem = q & 511;
        int r = rem >> 2, c = rem & 3;
        uint32_t dst = sbase + (uint32_t)op * 8192u + (uint32_t)(r * 64) + (uint32_t)((c ^ ((r >> 1) & 3)) * 16);
        const __nv_bfloat16* src;
        if (op == 0)      src = g_xth + (size_t)(a0 + r) * NX + k0 + c * 8;
        else if (op == 1) src = g_xtl + (size_t)(a0 + r) * NX + k0 + c * 8;
        else if (op == 2) src = g_xth + (size_t)(b0 + r) * NX + k0 + c * 8;
        else              src = g_xtl + (size_t)(b0 + r) * NX + k0 + c * 8;
        cp16(dst, src);
    }
}

__global__ void __launch_bounds__(256) gram_mma(int dummy) {
    extern __shared__ __align__(16) char dsm[];
    const uint32_t sb = smem_u32(dsm);
    const int tid = threadIdx.x, lane = tid & 31, wid = tid >> 5;
    const int a0 = c_pa[blockIdx.x] * 128;
    const int b0 = c_pb[blockIdx.x] * 128;
    const int kbase = blockIdx.y * 2048;
    const int wm = wid & 1, wn = wid >> 1;

    float c[4][4][4];
    #pragma unroll
    for (int mf = 0; mf < 4; mf++)
        #pragma unroll
        for (int nf = 0; nf < 4; nf++)
            #pragma unroll
            for (int r = 0; r < 4; r++) c[mf][nf][r] = 0.0f;

    load_stage_gram(sb,        a0, b0, kbase,      tid); cp_commit();
    load_stage_gram(sb + OSTG, a0, b0, kbase + 32, tid); cp_commit();

    const int a_row = wm * 64 + (lane & 15);
    const int a_kc  = (lane >> 4) & 1;
    const int b_row = wn * 32 + (lane & 7);
    const int b_kc  = (lane >> 3) & 1;

    int cs = 0, ls = 2;
    for (int it = 0; it < 64; it++) {
        cp_wait1();
        __syncthreads();
        int pf = it + 2; if (pf > 63) pf = 63;
        load_stage_gram(sb + (uint32_t)ls * OSTG, a0, b0, kbase + pf * 32, tid);
        cp_commit();
        const uint32_t sa = sb + (uint32_t)cs * OSTG;

        #pragma unroll
        for (int s = 0; s < 2; s++) {
            uint32_t ah[4][4], al[4][4];
            #pragma unroll
            for (int mf = 0; mf < 4; mf++) {
                int r = a_row + mf * 16;
                uint32_t addr = sa + (uint32_t)(r * 64) +
                                (uint32_t)((((s << 1) | a_kc) ^ ((r >> 1) & 3)) * 16);
                ldsm4(ah[mf][0], ah[mf][1], ah[mf][2], ah[mf][3], addr);
                ldsm4(al[mf][0], al[mf][1], al[mf][2], al[mf][3], addr + 8192u);
            }
            #pragma unroll
            for (int nf = 0; nf < 4; nf++) {
                int r = b_row + nf * 8;
                uint32_t base = (uint32_t)(r * 64) +
                                (uint32_t)((((s << 1) | b_kc) ^ ((r >> 1) & 3)) * 16);
                uint32_t bh0, bh1, bl0, bl1;
                ldsm2(bh0, bh1, sa + 16384u + base);
                ldsm2(bl0, bl1, sa + 24576u + base);
                #pragma unroll
                for (int mf = 0; mf < 4; mf++) {
                    mma16816bf(c[mf][nf], ah[mf], bh0, bh1);
                    mma16816bf(c[mf][nf], ah[mf], bl0, bl1);
                    mma16816bf(c[mf][nf], al[mf], bh0, bh1);
                }
            }
        }
        cs = (cs == 2) ? 0 : cs + 1;
        ls = (ls == 2) ? 0 : ls + 1;
    }
    cp_wait0();

    #pragma unroll
    for (int mf = 0; mf < 4; mf++) {
        int r0 = a0 + wm * 64 + mf * 16 + (lane >> 2);
        #pragma unroll
        for (int nf = 0; nf < 4; nf++) {
            int cb = b0 + wn * 32 + nf * 8 + (lane & 3) * 2;
            atomicAdd(&g_G[r0 * BLK + cb],           c[mf][nf][0]);
            atomicAdd(&g_G[r0 * BLK + cb + 1],       c[mf][nf][1]);
            atomicAdd(&g_G[(r0 + 8) * BLK + cb],     c[mf][nf][2]);
            atomicAdd(&g_G[(r0 + 8) * BLK + cb + 1], c[mf][nf][3]);
        }
    }
}

// ---------------- cov = G/n - m m^T + eps I (mirror upper from lower) ----------------
__global__ void cov_kernel() {
    int idx = blockIdx.x * blockDim.x + threadIdx.x;
    int a = idx >> 9, b = idx & 511;
    float graw = (a >= b) ? g_G[a * BLK + b] : g_G[b * BLK + a];
    float c = graw * (1.0f / (float)NX) - g_mean[a] * g_mean[b] + (a == b ? EPSV : 0.0f);
    g_C[idx] = c;
    float v = c * c;
    #pragma unroll
    for (int o = 16; o > 0; o >>= 1) v += __shfl_xor_sync(0xffffffffu, v, o);
    __shared__ float ws[8];
    int lane = threadIdx.x & 31, w = threadIdx.x >> 5;
    if (lane == 0) ws[w] = v;
    __syncthreads();
    if (w == 0) {
        float t = (lane < 8) ? ws[lane] : 0.0f;
        #pragma unroll
        for (int o = 4; o > 0; o >>= 1) t += __shfl_xor_sync(0xffffffffu, t, o);
        if (lane == 0) atomicAdd(&g_normSq, t);
    }
}

__global__ void scalars_kernel() {
    float norm = sqrtf(g_normSq);
    g_invNorm = 1.0f / norm;
    g_zscale = rsqrtf(norm);
}

__global__ void init_yz_kernel() {
    int idx = blockIdx.x * blockDim.x + threadIdx.x;
    int a = idx >> 9, b = idx & 511;
    g_Y[0][idx] = g_C[idx] * g_invNorm;
    g_Z[0][idx] = (a == b) ? 1.0f : 0.0f;
}

// ---------------- 512x512x512 GEMM core (SIMT, 64x64 tile) ----------------
__device__ __forceinline__ void mm512_tile(const float* __restrict__ A,
                                           const float* __restrict__ B,
                                           int m0, int n0, float acc[4][4]) {
    __shared__ float As[16][68];
    __shared__ float Bs[16][68];
    const int tid = threadIdx.x;
    const int tx = tid & 15, ty = tid >> 4;
    for (int k0 = 0; k0 < 512; k0 += 16) {
        #pragma unroll
        for (int i = 0; i < 4; i++) {
            int l = tid + i * 256;
            int m = l >> 4, k = l & 15;
            As[k][m] = A[(m0 + m) * 512 + k0 + k];
            int kb = l >> 6, n = l & 63;
            Bs[kb][n] = B[(k0 + kb) * 512 + n0 + n];
        }
        __syncthreads();
        #pragma unroll
        for (int k = 0; k < 16; k++) {
            float a[4], b[4];
            *(float4*)a = *(const float4*)&As[k][ty * 4];
            *(float4*)b = *(const float4*)&Bs[k][tx * 4];
            #pragma unroll
            for (int i = 0; i < 4; i++)
                #pragma unroll
                for (int j = 0; j < 4; j++) acc[i][j] += a[i] * b[j];
        }
        __syncthreads();
    }
}

__global__ void __launch_bounds__(256) ns_T_kernel(int cur) {
    const float* A = g_Z[cur];
    const float* B = g_Y[cur];
    int m0 = blockIdx.y * 64, n0 = blockIdx.x * 64;
    float acc[4][4] = {};
    mm512_tile(A, B, m0, n0, acc);
    int tx = threadIdx.x & 15, ty = threadIdx.x >> 4;
    #pragma unroll
    for (int i = 0; i < 4; i++)
        #pragma unroll
        for (int j = 0; j < 4; j++) {
            int r = m0 + ty * 4 + i, c = n0 + tx * 4 + j;
            g_T[r * 512 + c] = (r == c ? 1.5f : 0.0f) - 0.5f * acc[i][j];
        }
}

__global__ void __launch_bounds__(256) ns_pair_kernel(int cur) {
    const float* A; const float* B; float* C;
    if (blockIdx.z == 0) { A = g_Y[cur]; B = g_T; C = g_Y[cur ^ 1]; }
    else                 { A = g_T; B = g_Z[cur]; C = g_Z[cur ^ 1]; }
    int m0 = blockIdx.y * 64, n0 = blockIdx.x * 64;
    float acc[4][4] = {};
    mm512_tile(A, B, m0, n0, acc);
    int tx = threadIdx.x & 15, ty = threadIdx.x >> 4;
    #pragma unroll
    for (int i = 0; i < 4; i++)
        #pragma unroll
        for (int j = 0; j < 4; j++)
            C[(m0 + ty * 4 + i) * 512 + n0 + tx * 4 + j] = acc[i][j];
}

// ---------------- transpose-split Zfinal for fold_mma ----------------
__global__ void zt_split_kernel(int zfin) {
    const float* Zf = g_Z[zfin];
    int i = blockIdx.x * 256 + threadIdx.x;      // 1024 blocks
    int n = i >> 9, k = i & 511;
    float v = Zf[k * 512 + n];
    __nv_bfloat16 h = __float2bfloat16(v);
    g_zth[i] = h;
    g_ztl[i] = __float2bfloat16(v - __bfloat162float(h));
}

// ---------------- fold via mma bf16x3: Wf = (W8192x512 @ Zf) * zscale ----------------
__device__ __forceinline__ void load_stage_fold(uint32_t sbase, int m0, int n0, int k0, int tid) {
    #pragma unroll
    for (int i = 0; i < 8; i++) {
        int q = tid + i * 256;
        int op = q >> 9, rem = q & 511;
        int r = rem >> 2, c = rem & 3;
        uint32_t dst = sbase + (uint32_t)op * 8192u + (uint32_t)(r * 64) + (uint32_t)((c ^ ((r >> 1) & 3)) * 16);
        const __nv_bfloat16* src;
        if (op == 0)      src = g_vh  + (size_t)(m0 + r) * 512 + k0 + c * 8;
        else if (op == 1) src = g_vl  + (size_t)(m0 + r) * 512 + k0 + c * 8;
        else if (op == 2) src = g_zth + (size_t)(n0 + r) * 512 + k0 + c * 8;
        else              src = g_ztl + (size_t)(n0 + r) * 512 + k0 + c * 8;
        cp16(dst, src);
    }
}

__global__ void __launch_bounds__(256) fold_mma(int dummy) {
    extern __shared__ __align__(16) char dsm[];
    const uint32_t sb = smem_u32(dsm);
    const int tid = threadIdx.x, lane = tid & 31, wid = tid >> 5;
    const int n0 = blockIdx.x * 128;   // N = 512 -> 4
    const int m0 = blockIdx.y * 128;   // M = 8192 -> 64
    const int wm = wid & 1, wn = wid >> 1;

    float c[4][4][4];
    #pragma unroll
    for (int mf = 0; mf < 4; mf++)
        #pragma unroll
        for (int nf = 0; nf < 4; nf++)
            #pragma unroll
            for (int r = 0; r < 4; r++) c[mf][nf][r] = 0.0f;

    load_stage_fold(sb,        m0, n0, 0,  tid); cp_commit();
    load_stage_fold(sb + OSTG, m0, n0, 32, tid); cp_commit();

    const int a_row = wm * 64 + (lane & 15);
    const int a_kc  = (lane >> 4) & 1;
    const int b_row = wn * 32 + (lane & 7);
    const int b_kc  = (lane >> 3) & 1;

    int cs = 0, ls = 2;
    for (int it = 0; it < 16; it++) {            // K = 512, BK = 32
        cp_wait1();
        __syncthreads();
        int pf = it + 2; if (pf > 15) pf = 15;
        load_stage_fold(sb + (uint32_t)ls * OSTG, m0, n0, pf * 32, tid);
        cp_commit();
        const uint32_t sa = sb + (uint32_t)cs * OSTG;

        #pragma unroll
        for (int s = 0; s < 2; s++) {
            uint32_t ah[4][4], al[4][4];
            #pragma unroll
            for (int mf = 0; mf < 4; mf++) {
                int r = a_row + mf * 16;
                uint32_t addr = sa + (uint32_t)(r * 64) +
                                (uint32_t)((((s << 1) | a_kc) ^ ((r >> 1) & 3)) * 16);
                ldsm4(ah[mf][0], ah[mf][1], ah[mf][2], ah[mf][3], addr);
                ldsm4(al[mf][0], al[mf][1], al[mf][2], al[mf][3], addr + 8192u);
            }
            #pragma unroll
            for (int nf = 0; nf < 4; nf++) {
                int r = b_row + nf * 8;
                uint32_t base = (uint32_t)(r * 64) +
                                (uint32_t)((((s << 1) | b_kc) ^ ((r >> 1) & 3)) * 16);
                uint32_t bh0, bh1, bl0, bl1;
                ldsm2(bh0, bh1, sa + 16384u + base);
                ldsm2(bl0, bl1, sa + 24576u + base);
                #pragma unroll
                for (int mf = 0; mf < 4; mf++) {
                    mma16816bf(c[mf][nf], ah[mf], bh0, bh1);
                    mma16816bf(c[mf][nf], ah[mf], bl0, bl1);
                    mma16816bf(c[mf][nf], al[mf], bh0, bh1);
                }
            }
        }
        cs = (cs == 2) ? 0 : cs + 1;
        ls = (ls == 2) ? 0 : ls + 1;
    }
    cp_wait0();

    float sc = g_zscale;
    #pragma unroll
    for (int mf = 0; mf < 4; mf++) {
        int r0 = m0 + wm * 64 + mf * 16 + (lane >> 2);
        #pragma unroll
        for (int nf = 0; nf < 4; nf++) {
            int cb = n0 + wn * 32 + nf * 8 + (lane & 3) * 2;
            #pragma unroll
            for (int half = 0; half < 2; half++) {
                int row = r0 + half * 8;
                float w0 = c[mf][nf][half * 2 + 0] * sc;
                float w1 = c[mf][nf][half * 2 + 1] * sc;
                size_t idx = (size_t)row * 512 + cb;
                *(float2*)&g_Wf[idx] = make_float2(w0, w1);
                __nv_bfloat16 h0 = __float2bfloat16(w0), h1 = __float2bfloat16(w1);
                __nv_bfloat16 l0 = __float2bfloat16(w0 - __bfloat162float(h0));
                __nv_bfloat16 l1 = __float2bfloat16(w1 - __bfloat162float(h1));
                *(__nv_bfloat162*)(g_wh + idx) = __halves2bfloat162(h0, h1);
                *(__nv_bfloat162*)(g_wl + idx) = __halves2bfloat162(l0, l1);
            }
        }
    }
}

// ---------------- b_eff ----------------
__global__ void bias_kernel(const float* __restrict__ bias) {
    int o = blockIdx.x;
    int t = threadIdx.x;
    float s = 0.0f;
    for (int k = t; k < DIM; k += 256)
        s += g_Wf[o * DIM + k] * g_mean[k & 511];
    #pragma unroll
    for (int off = 16; off > 0; off >>= 1) s += __shfl_xor_sync(0xffffffffu, s, off);
    __shared__ float ws[8];
    int lane = t & 31, w = t >> 5;
    if (lane == 0) ws[w] = s;
    __syncthreads();
    if (t == 0) {
        float tot = 0.0f;
        #pragma unroll
        for (int i = 0; i < 8; i++) tot += ws[i];
        g_beff[o] = bias[o] - tot;
    }
}

// ---------------- main GEMM via mma bf16x3 (3-stage, BK=32) ----------------
__device__ __forceinline__ void load_stage_out(uint32_t sbase, int m0, int n0, int k0, int tid) {
    #pragma unroll
    for (int i = 0; i < 8; i++) {
        int q = tid + i * 256;
        int op = q >> 9, rem = q & 511;
        int r = rem >> 2, c = rem & 3;
        uint32_t dst = sbase + (uint32_t)op * 8192u + (uint32_t)(r * 64) + (uint32_t)((c ^ ((r >> 1) & 3)) * 16);
        const __nv_bfloat16* src;
        if (op == 0)      src = g_xh + (size_t)(m0 + r) * DIM + k0 + c * 8;
        else if (op == 1) src = g_xl + (size_t)(m0 + r) * DIM + k0 + c * 8;
        else if (op == 2) src = g_wh + (size_t)(n0 + r) * DIM + k0 + c * 8;
        else              src = g_wl + (size_t)(n0 + r) * DIM + k0 + c * 8;
        cp16(dst, src);
    }
}

__global__ void __launch_bounds__(256) out_gemm_mma(float* __restrict__ out) {
    extern __shared__ __align__(16) char dsm[];
    const uint32_t sb = smem_u32(dsm);
    float* sbias = (float*)(dsm + 3 * OSTG);
    const int tid = threadIdx.x, lane = tid & 31, wid = tid >> 5;
    const int n0 = blockIdx.x * 128, m0 = blockIdx.y * 128;
    const int wm = wid & 1, wn = wid >> 1;

    if (tid < 128) sbias[tid] = g_beff[n0 + tid];

    float c[4][4][4];
    #pragma unroll
    for (int mf = 0; mf < 4; mf++)
        #pragma unroll
        for (int nf = 0; nf < 4; nf++)
            #pragma unroll
            for (int r = 0; r < 4; r++) c[mf][nf][r] = 0.0f;

    load_stage_out(sb,        m0, n0, 0,  tid); cp_commit();
    load_stage_out(sb + OSTG, m0, n0, 32, tid); cp_commit();

    const int a_row = wm * 64 + (lane & 15);
    const int a_kc  = (lane >> 4) & 1;
    const int b_row = wn * 32 + (lane & 7);
    const int b_kc  = (lane >> 3) & 1;

    int cs = 0, ls = 2;
    for (int it = 0; it < 64; it++) {
        cp_wait1();
        __syncthreads();
        int pf = it + 2; if (pf > 63) pf = 63;
        load_stage_out(sb + (uint32_t)ls * OSTG, m0, n0, pf * 32, tid);
        cp_commit();
        const uint32_t sa = sb + (uint32_t)cs * OSTG;

        #pragma unroll
        for (int s = 0; s < 2; s++) {
            uint32_t ah[4][4], al[4][4];
            #pragma unroll
            for (int mf = 0; mf < 4; mf++) {
                int r = a_row + mf * 16;
                uint32_t addr = sa + (uint32_t)(r * 64) +
                                (uint32_t)((((s << 1) | a_kc) ^ ((r >> 1) & 3)) * 16);
                ldsm4(ah[mf][0], ah[mf][1], ah[mf][2], ah[mf][3], addr);
                ldsm4(al[mf][0], al[mf][1], al[mf][2], al[mf][3], addr + 8192u);
            }
            #pragma unroll
            for (int nf = 0; nf < 4; nf++) {
                int r = b_row + nf * 8;
                uint32_t base = (uint32_t)(r * 64) +
                                (uint32_t)((((s << 1) | b_kc) ^ ((r >> 1) & 3)) * 16);
                uint32_t bh0, bh1, bl0, bl1;
                ldsm2(bh0, bh1, sa + 16384u + base);
                ldsm2(bl0, bl1, sa + 24576u + base);
                #pragma unroll
                for (int mf = 0; mf < 4; mf++) {
                    mma16816bf(c[mf][nf], ah[mf], bh0, bh1);
                    mma16816bf(c[mf][nf], ah[mf], bl0, bl1);
                    mma16816bf(c[mf][nf], al[mf], bh0, bh1);
                }
            }
        }
        cs = (cs == 2) ? 0 : cs + 1;
        ls = (ls == 2) ? 0 : ls + 1;
    }
    cp_wait0();

    #pragma unroll
    for (int mf = 0; mf < 4; mf++) {
        int r0 = m0 + wm * 64 + mf * 16 + (lane >> 2);
        #pragma unroll
        for (int nf = 0; nf < 4; nf++) {
            int cb = wn * 32 + nf * 8 + (lane & 3) * 2;
            float2 v0, v1;
            v0.x = c[mf][nf][0] + sbias[cb];
            v0.y = c[mf][nf][1] + sbias[cb + 1];
            v1.x = c[mf][nf][2] + sbias[cb];
            v1.y = c[mf][nf][3] + sbias[cb + 1];
            *(float2*)&out[(size_t)r0 * DIM + n0 + cb] = v0;
            *(float2*)&out[(size_t)(r0 + 8) * DIM + n0 + cb] = v1;
        }
    }
}

// ---------------- host orchestration ----------------
extern "C" void kernel_launch(void* const* d_in, const int* in_sizes, int n_in,
                              void* d_out, int out_size) {
    const float* x      = (const float*)d_in[0];
    const float* weight = (const float*)d_in[1];
    const float* bias   = (const float*)d_in[2];
    float* out          = (float*)d_out;

    cudaFuncSetAttribute(gram_mma,     cudaFuncAttributeMaxDynamicSharedMemorySize, 3 * OSTG);
    cudaFuncSetAttribute(fold_mma,     cudaFuncAttributeMaxDynamicSharedMemorySize, 3 * OSTG);
    cudaFuncSetAttribute(out_gemm_mma, cudaFuncAttributeMaxDynamicSharedMemorySize, 3 * OSTG + 512);

    zero_kernel<<<1026, 256>>>();
    xprep_kernel<<<dim3(2048, 8), 256>>>(x);
    mean_scale_kernel<<<1, 512>>>();
    split_v_kernel<<<4096, 256>>>(weight);
    gram_mma<<<dim3(10, 64), 256, 3 * OSTG>>>(0);
    cov_kernel<<<1024, 256>>>();
    scalars_kernel<<<1, 1>>>();
    init_yz_kernel<<<1024, 256>>>();

    int cur = 0;
    for (int it = 0; it < NITER; it++) {
        ns_T_kernel<<<dim3(8, 8), 256>>>(cur);
        ns_pair_kernel<<<dim3(8, 8, 2), 256>>>(cur);
        cur ^= 1;
    }

    zt_split_kernel<<<1024, 256>>>(cur);
    fold_mma<<<dim3(4, 64), 256, 3 * OSTG>>>(0);
    bias_kernel<<<DIM, 256>>>(bias);
    out_gemm_mma<<<dim3(16, 256), 256, 3 * OSTG + 512>>>(out);
}

// round 13
// speedup vs baseline: 1.1094x; 1.0977x over previous
#include <cuda_runtime.h>
#include <cuda_bf16.h>
#include <math.h>
#include <stdint.h>

// Problem constants
#define NROWS 32768
#define DIM   2048
#define BLK   512
#define NX    (NROWS * DIM / BLK)   // 131072 rows of X
#define EPSV  1e-5f
#define NITER 5

// ---------------- device scratch (no allocations allowed) ----------------
__device__ float g_meanAcc[BLK];
__device__ float g_mean[BLK];
__device__ float g_G[BLK * BLK];
__device__ float g_C[BLK * BLK];
__device__ float g_Y[2][BLK * BLK];
__device__ float g_Z[2][BLK * BLK];
__device__ float g_T[BLK * BLK];
__device__ float g_normSq;
__device__ float g_invNorm;
__device__ float g_zscale;
__device__ float g_Wf[DIM * DIM];      // folded weight fp32
__device__ float g_beff[DIM];

// bf16 hi/lo splits
__device__ __nv_bfloat16 g_xh[(size_t)NROWS * DIM];
__device__ __nv_bfloat16 g_xl[(size_t)NROWS * DIM];
__device__ __nv_bfloat16 g_wh[(size_t)DIM * DIM];
__device__ __nv_bfloat16 g_wl[(size_t)DIM * DIM];
// transposed splits of X (view [131072,512] -> store [512][131072])
__device__ __nv_bfloat16 g_xth[(size_t)BLK * NX];
__device__ __nv_bfloat16 g_xtl[(size_t)BLK * NX];

// symmetric gram tile pairs (lower triangle, 10 of 16)
__constant__ int c_pa[10] = {0,1,1,2,2,2,3,3,3,3};
__constant__ int c_pb[10] = {0,0,1,0,1,2,0,1,2,3};

// ---------------- PTX helpers (sm_80+ features only) ----------------
__device__ __forceinline__ uint32_t smem_u32(const void* p) {
    uint32_t a;
    asm("{ .reg .u64 t; cvta.to.shared.u64 t, %1; cvt.u32.u64 %0, t; }" : "=r"(a) : "l"(p));
    return a;
}
__device__ __forceinline__ void cp16(uint32_t d, const void* s) {
    asm volatile("cp.async.cg.shared.global [%0], [%1], 16;" :: "r"(d), "l"(s));
}
__device__ __forceinline__ void cp_commit() { asm volatile("cp.async.commit_group;"); }
__device__ __forceinline__ void cp_wait0()  { asm volatile("cp.async.wait_group 0;"); }
__device__ __forceinline__ void cp_wait1()  { asm volatile("cp.async.wait_group 1;"); }

__device__ __forceinline__ void ldsm4(uint32_t& r0, uint32_t& r1, uint32_t& r2, uint32_t& r3, uint32_t a) {
    asm volatile("ldmatrix.sync.aligned.m8n8.x4.shared.b16 {%0,%1,%2,%3}, [%4];"
                 : "=r"(r0), "=r"(r1), "=r"(r2), "=r"(r3) : "r"(a));
}
__device__ __forceinline__ void ldsm2(uint32_t& r0, uint32_t& r1, uint32_t a) {
    asm volatile("ldmatrix.sync.aligned.m8n8.x2.shared.b16 {%0,%1}, [%2];"
                 : "=r"(r0), "=r"(r1) : "r"(a));
}
__device__ __forceinline__ void mma16816bf(float* c, const uint32_t* a, uint32_t b0, uint32_t b1) {
    asm volatile("mma.sync.aligned.m16n8k16.row.col.f32.bf16.bf16.f32 "
                 "{%0,%1,%2,%3}, {%4,%5,%6,%7}, {%8,%9}, {%0,%1,%2,%3};"
                 : "+f"(c[0]), "+f"(c[1]), "+f"(c[2]), "+f"(c[3])
                 : "r"(a[0]), "r"(a[1]), "r"(a[2]), "r"(a[3]), "r"(b0), "r"(b1));
}

// ---------------- zero accumulators ----------------
__global__ void zero_kernel() {
    int idx = blockIdx.x * blockDim.x + threadIdx.x;
    int total = BLK * BLK + BLK + 1;
    for (int i = idx; i < total; i += gridDim.x * blockDim.x) {
        if (i < BLK * BLK) g_G[i] = 0.0f;
        else if (i < BLK * BLK + BLK) g_meanAcc[i - BLK * BLK] = 0.0f;
        else g_normSq = 0.0f;
    }
}

// ---------------- bf16 hi/lo split of x (row-major) ----------------
__global__ void split_x_kernel(const float* __restrict__ x) {
    size_t i = ((size_t)blockIdx.x * 256 + threadIdx.x) * 4;
    float4 v = *(const float4*)(x + i);
    __nv_bfloat16 h0 = __float2bfloat16(v.x), h1 = __float2bfloat16(v.y);
    __nv_bfloat16 h2 = __float2bfloat16(v.z), h3 = __float2bfloat16(v.w);
    __nv_bfloat16 l0 = __float2bfloat16(v.x - __bfloat162float(h0));
    __nv_bfloat16 l1 = __float2bfloat16(v.y - __bfloat162float(h1));
    __nv_bfloat16 l2 = __float2bfloat16(v.z - __bfloat162float(h2));
    __nv_bfloat16 l3 = __float2bfloat16(v.w - __bfloat162float(h3));
    *(__nv_bfloat162*)(g_xh + i)     = __halves2bfloat162(h0, h1);
    *(__nv_bfloat162*)(g_xh + i + 2) = __halves2bfloat162(h2, h3);
    *(__nv_bfloat162*)(g_xl + i)     = __halves2bfloat162(l0, l1);
    *(__nv_bfloat162*)(g_xl + i + 2) = __halves2bfloat162(l2, l3);
}

// ---------------- bf16 hi/lo split of folded weight ----------------
__global__ void split_w_kernel() {
    size_t i = ((size_t)blockIdx.x * 256 + threadIdx.x) * 4;
    float4 v = *(const float4*)(g_Wf + i);
    __nv_bfloat16 h0 = __float2bfloat16(v.x), h1 = __float2bfloat16(v.y);
    __nv_bfloat16 h2 = __float2bfloat16(v.z), h3 = __float2bfloat16(v.w);
    __nv_bfloat16 l0 = __float2bfloat16(v.x - __bfloat162float(h0));
    __nv_bfloat16 l1 = __float2bfloat16(v.y - __bfloat162float(h1));
    __nv_bfloat16 l2 = __float2bfloat16(v.z - __bfloat162float(h2));
    __nv_bfloat16 l3 = __float2bfloat16(v.w - __bfloat162float(h3));
    *(__nv_bfloat162*)(g_wh + i)     = __halves2bfloat162(h0, h1);
    *(__nv_bfloat162*)(g_wh + i + 2) = __halves2bfloat162(h2, h3);
    *(__nv_bfloat162*)(g_wl + i)     = __halves2bfloat162(l0, l1);
    *(__nv_bfloat162*)(g_wl + i + 2) = __halves2bfloat162(l2, l3);
}

// ---------------- transposed bf16 hi/lo split: X[131072][512] -> xt[512][131072] ----------------
__global__ void __launch_bounds__(256) split_xt_kernel(const float* __restrict__ x) {
    __shared__ float tile[64][65];
    const int tid = threadIdx.x;
    const int r0 = blockIdx.x * 64;
    const int c0 = blockIdx.y * 64;
    #pragma unroll
    for (int i = 0; i < 4; i++) {
        int r = i * 16 + (tid >> 4);
        int c = (tid & 15) * 4;
        float4 v = *(const float4*)(x + (size_t)(r0 + r) * BLK + c0 + c);
        tile[r][c] = v.x; tile[r][c + 1] = v.y; tile[r][c + 2] = v.z; tile[r][c + 3] = v.w;
    }
    __syncthreads();
    #pragma unroll
    for (int i = 0; i < 4; i++) {
        int cc = i * 16 + (tid >> 4);
        int r = (tid & 15) * 4;
        float v0 = tile[r][cc], v1 = tile[r + 1][cc], v2 = tile[r + 2][cc], v3 = tile[r + 3][cc];
        __nv_bfloat16 h0 = __float2bfloat16(v0), h1 = __float2bfloat16(v1);
        __nv_bfloat16 h2 = __float2bfloat16(v2), h3 = __float2bfloat16(v3);
        __nv_bfloat16 l0 = __float2bfloat16(v0 - __bfloat162float(h0));
        __nv_bfloat16 l1 = __float2bfloat16(v1 - __bfloat162float(h1));
        __nv_bfloat16 l2 = __float2bfloat16(v2 - __bfloat162float(h2));
        __nv_bfloat16 l3 = __float2bfloat16(v3 - __bfloat162float(h3));
        size_t o = (size_t)(c0 + cc) * NX + r0 + r;
        *(__nv_bfloat162*)(g_xth + o)     = __halves2bfloat162(h0, h1);
        *(__nv_bfloat162*)(g_xth + o + 2) = __halves2bfloat162(h2, h3);
        *(__nv_bfloat162*)(g_xtl + o)     = __halves2bfloat162(l0, l1);
        *(__nv_bfloat162*)(g_xtl + o + 2) = __halves2bfloat162(l2, l3);
    }
}

// ---------------- column means ----------------
__global__ void col_mean_kernel(const float* __restrict__ x) {
    int t = threadIdx.x;
    int rbase = blockIdx.x * 512;
    float s = 0.0f;
    const float* p = x + (size_t)rbase * BLK + t;
    #pragma unroll 8
    for (int r = 0; r < 512; r++) s += p[(size_t)r * BLK];
    atomicAdd(&g_meanAcc[t], s);
}

__global__ void mean_scale_kernel() {
    int t = threadIdx.x;
    g_mean[t] = g_meanAcc[t] * (1.0f / (float)NX);
}

// ============ MMA tile machinery: BK=32, 64B rows, 4-chunk XOR swizzle ============
#define OSTG 32768

// ---------------- gram via mma bf16x3 ----------------
__device__ __forceinline__ void load_stage_gram(uint32_t sbase, int a0, int b0, int k0, int tid) {
    #pragma unroll
    for (int i = 0; i < 8; i++) {
        int q = tid + i * 256;
        int op = q >> 9, rem = q & 511;
        int r = rem >> 2, c = rem & 3;
        uint32_t dst = sbase + (uint32_t)op * 8192u + (uint32_t)(r * 64) + (uint32_t)((c ^ ((r >> 1) & 3)) * 16);
        const __nv_bfloat16* src;
        if (op == 0)      src = g_xth + (size_t)(a0 + r) * NX + k0 + c * 8;
        else if (op == 1) src = g_xtl + (size_t)(a0 + r) * NX + k0 + c * 8;
        else if (op == 2) src = g_xth + (size_t)(b0 + r) * NX + k0 + c * 8;
        else              src = g_xtl + (size_t)(b0 + r) * NX + k0 + c * 8;
        cp16(dst, src);
    }
}

__global__ void __launch_bounds__(256, 2) gram_mma(int dummy) {
    extern __shared__ __align__(16) char dsm[];
    const uint32_t sb = smem_u32(dsm);
    const int tid = threadIdx.x, lane = tid & 31, wid = tid >> 5;
    const int a0 = c_pa[blockIdx.x] * 128;
    const int b0 = c_pb[blockIdx.x] * 128;
    const int kbase = blockIdx.y * 2048;
    const int wm = wid & 1, wn = wid >> 1;

    float c[4][4][4];
    #pragma unroll
    for (int mf = 0; mf < 4; mf++)
        #pragma unroll
        for (int nf = 0; nf < 4; nf++)
            #pragma unroll
            for (int r = 0; r < 4; r++) c[mf][nf][r] = 0.0f;

    load_stage_gram(sb,        a0, b0, kbase,      tid); cp_commit();
    load_stage_gram(sb + OSTG, a0, b0, kbase + 32, tid); cp_commit();

    const int a_row = wm * 64 + (lane & 15);
    const int a_kc  = (lane >> 4) & 1;
    const int b_row = wn * 32 + (lane & 7);
    const int b_kc  = (lane >> 3) & 1;

    int cs = 0, ls = 2;
    for (int it = 0; it < 64; it++) {
        cp_wait1();
        __syncthreads();
        int pf = it + 2; if (pf > 63) pf = 63;
        load_stage_gram(sb + (uint32_t)ls * OSTG, a0, b0, kbase + pf * 32, tid);
        cp_commit();
        const uint32_t sa = sb + (uint32_t)cs * OSTG;

        #pragma unroll
        for (int s = 0; s < 2; s++) {
            uint32_t ah[4][4], al[4][4];
            #pragma unroll
            for (int mf = 0; mf < 4; mf++) {
                int r = a_row + mf * 16;
                uint32_t addr = sa + (uint32_t)(r * 64) +
                                (uint32_t)((((s << 1) | a_kc) ^ ((r >> 1) & 3)) * 16);
                ldsm4(ah[mf][0], ah[mf][1], ah[mf][2], ah[mf][3], addr);
                ldsm4(al[mf][0], al[mf][1], al[mf][2], al[mf][3], addr + 8192u);
            }
            #pragma unroll
            for (int nf = 0; nf < 4; nf++) {
                int r = b_row + nf * 8;
                uint32_t base = (uint32_t)(r * 64) +
                                (uint32_t)((((s << 1) | b_kc) ^ ((r >> 1) & 3)) * 16);
                uint32_t bh0, bh1, bl0, bl1;
                ldsm2(bh0, bh1, sa + 16384u + base);
                ldsm2(bl0, bl1, sa + 24576u + base);
                #pragma unroll
                for (int mf = 0; mf < 4; mf++) {
                    mma16816bf(c[mf][nf], ah[mf], bh0, bh1);
                    mma16816bf(c[mf][nf], ah[mf], bl0, bl1);
                    mma16816bf(c[mf][nf], al[mf], bh0, bh1);
                }
            }
        }
        cs = (cs == 2) ? 0 : cs + 1;
        ls = (ls == 2) ? 0 : ls + 1;
    }
    cp_wait0();

    #pragma unroll
    for (int mf = 0; mf < 4; mf++) {
        int r0 = a0 + wm * 64 + mf * 16 + (lane >> 2);
        #pragma unroll
        for (int nf = 0; nf < 4; nf++) {
            int cb = b0 + wn * 32 + nf * 8 + (lane & 3) * 2;
            atomicAdd(&g_G[r0 * BLK + cb],           c[mf][nf][0]);
            atomicAdd(&g_G[r0 * BLK + cb + 1],       c[mf][nf][1]);
            atomicAdd(&g_G[(r0 + 8) * BLK + cb],     c[mf][nf][2]);
            atomicAdd(&g_G[(r0 + 8) * BLK + cb + 1], c[mf][nf][3]);
        }
    }
}

// ---------------- cov = G/n - m m^T + eps I (mirror upper from lower) ----------------
__global__ void cov_kernel() {
    int idx = blockIdx.x * blockDim.x + threadIdx.x;
    int a = idx >> 9, b = idx & 511;
    float graw = (a >= b) ? g_G[a * BLK + b] : g_G[b * BLK + a];
    float c = graw * (1.0f / (float)NX) - g_mean[a] * g_mean[b] + (a == b ? EPSV : 0.0f);
    g_C[idx] = c;
    float v = c * c;
    #pragma unroll
    for (int o = 16; o > 0; o >>= 1) v += __shfl_xor_sync(0xffffffffu, v, o);
    __shared__ float ws[8];
    int lane = threadIdx.x & 31, w = threadIdx.x >> 5;
    if (lane == 0) ws[w] = v;
    __syncthreads();
    if (w == 0) {
        float t = (lane < 8) ? ws[lane] : 0.0f;
        #pragma unroll
        for (int o = 4; o > 0; o >>= 1) t += __shfl_xor_sync(0xffffffffu, t, o);
        if (lane == 0) atomicAdd(&g_normSq, t);
    }
}

__global__ void scalars_kernel() {
    float norm = sqrtf(g_normSq);
    g_invNorm = 1.0f / norm;
    g_zscale = rsqrtf(norm);
}

__global__ void init_yz_kernel() {
    int idx = blockIdx.x * blockDim.x + threadIdx.x;
    int a = idx >> 9, b = idx & 511;
    g_Y[0][idx] = g_C[idx] * g_invNorm;
    g_Z[0][idx] = (a == b) ? 1.0f : 0.0f;
}

// ---------------- 512x512x512 GEMM core (SIMT, 64x64 tile) ----------------
__device__ __forceinline__ void mm512_tile(const float* __restrict__ A,
                                           const float* __restrict__ B,
                                           int m0, int n0, float acc[4][4]) {
    __shared__ float As[16][68];
    __shared__ float Bs[16][68];
    const int tid = threadIdx.x;
    const int tx = tid & 15, ty = tid >> 4;
    for (int k0 = 0; k0 < 512; k0 += 16) {
        #pragma unroll
        for (int i = 0; i < 4; i++) {
            int l = tid + i * 256;
            int m = l >> 4, k = l & 15;
            As[k][m] = A[(m0 + m) * 512 + k0 + k];
            int kb = l >> 6, n = l & 63;
            Bs[kb][n] = B[(k0 + kb) * 512 + n0 + n];
        }
        __syncthreads();
        #pragma unroll
        for (int k = 0; k < 16; k++) {
            float a[4], b[4];
            *(float4*)a = *(const float4*)&As[k][ty * 4];
            *(float4*)b = *(const float4*)&Bs[k][tx * 4];
            #pragma unroll
            for (int i = 0; i < 4; i++)
                #pragma unroll
                for (int j = 0; j < 4; j++) acc[i][j] += a[i] * b[j];
        }
        __syncthreads();
    }
}

__global__ void __launch_bounds__(256) ns_T_kernel(int cur) {
    const float* A = g_Z[cur];
    const float* B = g_Y[cur];
    int m0 = blockIdx.y * 64, n0 = blockIdx.x * 64;
    float acc[4][4] = {};
    mm512_tile(A, B, m0, n0, acc);
    int tx = threadIdx.x & 15, ty = threadIdx.x >> 4;
    #pragma unroll
    for (int i = 0; i < 4; i++)
        #pragma unroll
        for (int j = 0; j < 4; j++) {
            int r = m0 + ty * 4 + i, c = n0 + tx * 4 + j;
            g_T[r * 512 + c] = (r == c ? 1.5f : 0.0f) - 0.5f * acc[i][j];
        }
}

__global__ void __launch_bounds__(256) ns_pair_kernel(int cur) {
    const float* A; const float* B; float* C;
    if (blockIdx.z == 0) { A = g_Y[cur]; B = g_T; C = g_Y[cur ^ 1]; }
    else                 { A = g_T; B = g_Z[cur]; C = g_Z[cur ^ 1]; }
    int m0 = blockIdx.y * 64, n0 = blockIdx.x * 64;
    float acc[4][4] = {};
    mm512_tile(A, B, m0, n0, acc);
    int tx = threadIdx.x & 15, ty = threadIdx.x >> 4;
    #pragma unroll
    for (int i = 0; i < 4; i++)
        #pragma unroll
        for (int j = 0; j < 4; j++)
            C[(m0 + ty * 4 + i) * 512 + n0 + tx * 4 + j] = acc[i][j];
}

// ---------------- fold: Wf = (weight.reshape(8192,512) @ Zfinal) * zscale ----------------
__global__ void __launch_bounds__(256) fold_kernel(const float* __restrict__ W, int zfin) {
    __shared__ float As[16][132];
    __shared__ float Bs[16][132];
    const float* Zf = g_Z[zfin];
    const int n0 = blockIdx.x * 128;
    const int m0 = blockIdx.y * 128;
    const int tid = threadIdx.x;
    const int tx = tid & 15, ty = tid >> 4;
    float acc[8][8];
    #pragma unroll
    for (int i = 0; i < 8; i++)
        #pragma unroll
        for (int j = 0; j < 8; j++) acc[i][j] = 0.0f;

    for (int k0 = 0; k0 < 512; k0 += 16) {
        #pragma unroll
        for (int i = 0; i < 8; i++) {
            int l = tid + i * 256;
            int r = l >> 4, k = l & 15;
            As[k][r] = W[(m0 + r) * 512 + k0 + k];
            int kb = l >> 7, c = l & 127;
            Bs[kb][c] = Zf[(k0 + kb) * 512 + n0 + c];
        }
        __syncthreads();
        #pragma unroll
        for (int k = 0; k < 16; k++) {
            float a[8], b[8];
            *(float4*)(a)     = *(const float4*)&As[k][ty * 8];
            *(float4*)(a + 4) = *(const float4*)&As[k][ty * 8 + 4];
            *(float4*)(b)     = *(const float4*)&Bs[k][tx * 8];
            *(float4*)(b + 4) = *(const float4*)&Bs[k][tx * 8 + 4];
            #pragma unroll
            for (int i = 0; i < 8; i++)
                #pragma unroll
                for (int j = 0; j < 8; j++) acc[i][j] += a[i] * b[j];
        }
        __syncthreads();
    }
    float s = g_zscale;
    #pragma unroll
    for (int i = 0; i < 8; i++)
        #pragma unroll
        for (int j = 0; j < 8; j++)
            g_Wf[(m0 + ty * 8 + i) * 512 + n0 + tx * 8 + j] = acc[i][j] * s;
}

// ---------------- b_eff ----------------
__global__ void bias_kernel(const float* __restrict__ bias) {
    int o = blockIdx.x;
    int t = threadIdx.x;
    float s = 0.0f;
    for (int k = t; k < DIM; k += 256)
        s += g_Wf[o * DIM + k] * g_mean[k & 511];
    #pragma unroll
    for (int off = 16; off > 0; off >>= 1) s += __shfl_xor_sync(0xffffffffu, s, off);
    __shared__ float ws[8];
    int lane = t & 31, w = t >> 5;
    if (lane == 0) ws[w] = s;
    __syncthreads();
    if (t == 0) {
        float tot = 0.0f;
        #pragma unroll
        for (int i = 0; i < 8; i++) tot += ws[i];
        g_beff[o] = bias[o] - tot;
    }
}

// ---------------- main GEMM via mma bf16x3 (3-stage, BK=32, 2 CTAs/SM) ----------------
__device__ __forceinline__ void load_stage_out(uint32_t sbase, int m0, int n0, int k0, int tid) {
    #pragma unroll
    for (int i = 0; i < 8; i++) {
        int q = tid + i * 256;
        int op = q >> 9, rem = q & 511;
        int r = rem >> 2, c = rem & 3;
        uint32_t dst = sbase + (uint32_t)op * 8192u + (uint32_t)(r * 64) + (uint32_t)((c ^ ((r >> 1) & 3)) * 16);
        const __nv_bfloat16* src;
        if (op == 0)      src = g_xh + (size_t)(m0 + r) * DIM + k0 + c * 8;
        else if (op == 1) src = g_xl + (size_t)(m0 + r) * DIM + k0 + c * 8;
        else if (op == 2) src = g_wh + (size_t)(n0 + r) * DIM + k0 + c * 8;
        else              src = g_wl + (size_t)(n0 + r) * DIM + k0 + c * 8;
        cp16(dst, src);
    }
}

__global__ void __launch_bounds__(256, 2) out_gemm_mma(float* __restrict__ out) {
    extern __shared__ __align__(16) char dsm[];
    const uint32_t sb = smem_u32(dsm);
    float* sbias = (float*)(dsm + 3 * OSTG);
    const int tid = threadIdx.x, lane = tid & 31, wid = tid >> 5;
    const int n0 = blockIdx.x * 128, m0 = blockIdx.y * 128;
    const int wm = wid & 1, wn = wid >> 1;

    if (tid < 128) sbias[tid] = g_beff[n0 + tid];

    float c[4][4][4];
    #pragma unroll
    for (int mf = 0; mf < 4; mf++)
        #pragma unroll
        for (int nf = 0; nf < 4; nf++)
            #pragma unroll
            for (int r = 0; r < 4; r++) c[mf][nf][r] = 0.0f;

    load_stage_out(sb,        m0, n0, 0,  tid); cp_commit();
    load_stage_out(sb + OSTG, m0, n0, 32, tid); cp_commit();

    const int a_row = wm * 64 + (lane & 15);
    const int a_kc  = (lane >> 4) & 1;
    const int b_row = wn * 32 + (lane & 7);
    const int b_kc  = (lane >> 3) & 1;

    int cs = 0, ls = 2;
    for (int it = 0; it < 64; it++) {
        cp_wait1();
        __syncthreads();
        int pf = it + 2; if (pf > 63) pf = 63;
        load_stage_out(sb + (uint32_t)ls * OSTG, m0, n0, pf * 32, tid);
        cp_commit();
        const uint32_t sa = sb + (uint32_t)cs * OSTG;

        #pragma unroll
        for (int s = 0; s < 2; s++) {
            uint32_t ah[4][4], al[4][4];
            #pragma unroll
            for (int mf = 0; mf < 4; mf++) {
                int r = a_row + mf * 16;
                uint32_t addr = sa + (uint32_t)(r * 64) +
                                (uint32_t)((((s << 1) | a_kc) ^ ((r >> 1) & 3)) * 16);
                ldsm4(ah[mf][0], ah[mf][1], ah[mf][2], ah[mf][3], addr);
                ldsm4(al[mf][0], al[mf][1], al[mf][2], al[mf][3], addr + 8192u);
            }
            #pragma unroll
            for (int nf = 0; nf < 4; nf++) {
                int r = b_row + nf * 8;
                uint32_t base = (uint32_t)(r * 64) +
                                (uint32_t)((((s << 1) | b_kc) ^ ((r >> 1) & 3)) * 16);
                uint32_t bh0, bh1, bl0, bl1;
                ldsm2(bh0, bh1, sa + 16384u + base);
                ldsm2(bl0, bl1, sa + 24576u + base);
                #pragma unroll
                for (int mf = 0; mf < 4; mf++) {
                    mma16816bf(c[mf][nf], ah[mf], bh0, bh1);
                    mma16816bf(c[mf][nf], ah[mf], bl0, bl1);
                    mma16816bf(c[mf][nf], al[mf], bh0, bh1);
                }
            }
        }
        cs = (cs == 2) ? 0 : cs + 1;
        ls = (ls == 2) ? 0 : ls + 1;
    }
    cp_wait0();

    #pragma unroll
    for (int mf = 0; mf < 4; mf++) {
        int r0 = m0 + wm * 64 + mf * 16 + (lane >> 2);
        #pragma unroll
        for (int nf = 0; nf < 4; nf++) {
            int cb = wn * 32 + nf * 8 + (lane & 3) * 2;
            float2 v0, v1;
            v0.x = c[mf][nf][0] + sbias[cb];
            v0.y = c[mf][nf][1] + sbias[cb + 1];
            v1.x = c[mf][nf][2] + sbias[cb];
            v1.y = c[mf][nf][3] + sbias[cb + 1];
            *(float2*)&out[(size_t)r0 * DIM + n0 + cb] = v0;
            *(float2*)&out[(size_t)(r0 + 8) * DIM + n0 + cb] = v1;
        }
    }
}

// ---------------- host orchestration ----------------
extern "C" void kernel_launch(void* const* d_in, const int* in_sizes, int n_in,
                              void* d_out, int out_size) {
    const float* x      = (const float*)d_in[0];
    const float* weight = (const float*)d_in[1];
    const float* bias   = (const float*)d_in[2];
    float* out          = (float*)d_out;

    cudaFuncSetAttribute(gram_mma,     cudaFuncAttributeMaxDynamicSharedMemorySize, 3 * OSTG);
    cudaFuncSetAttribute(out_gemm_mma, cudaFuncAttributeMaxDynamicSharedMemorySize, 3 * OSTG + 512);

    zero_kernel<<<1026, 256>>>();
    split_x_kernel<<<65536, 256>>>(x);
    split_xt_kernel<<<dim3(2048, 8), 256>>>(x);
    col_mean_kernel<<<256, 512>>>(x);
    mean_scale_kernel<<<1, 512>>>();
    gram_mma<<<dim3(10, 64), 256, 3 * OSTG>>>(0);
    cov_kernel<<<1024, 256>>>();
    scalars_kernel<<<1, 1>>>();
    init_yz_kernel<<<1024, 256>>>();

    int cur = 0;
    for (int it = 0; it < NITER; it++) {
        ns_T_kernel<<<dim3(8, 8), 256>>>(cur);
        ns_pair_kernel<<<dim3(8, 8, 2), 256>>>(cur);
        cur ^= 1;
    }

    fold_kernel<<<dim3(4, 64), 256>>>(weight, cur);
    bias_kernel<<<DIM, 256>>>(bias);
    split_w_kernel<<<4096, 256>>>();

    out_gemm_mma<<<dim3(16, 256), 256, 3 * OSTG + 512>>>(out);
}

// round 14
// speedup vs baseline: 1.1489x; 1.0357x over previous
#include <cuda_runtime.h>
#include <cuda_bf16.h>
#include <math.h>
#include <stdint.h>

// Problem constants
#define NROWS 32768
#define DIM   2048
#define BLK   512
#define NX    (NROWS * DIM / BLK)   // 131072 rows of X
#define EPSV  1e-5f
#define NITER 5

// ---------------- device scratch (no allocations allowed) ----------------
__device__ float g_meanAcc[BLK];
__device__ float g_mean[BLK];
__device__ float g_G[BLK * BLK];
__device__ float g_C[BLK * BLK];
__device__ float g_Y[2][BLK * BLK];
__device__ float g_Z[2][BLK * BLK];
__device__ float g_T[BLK * BLK];
__device__ float g_normSq;
__device__ float g_invNorm;
__device__ float g_zscale;
__device__ float g_Wf[DIM * DIM];      // folded weight fp32
__device__ float g_beff[DIM];

// bf16 hi/lo splits
__device__ __nv_bfloat16 g_xh[(size_t)NROWS * DIM];
__device__ __nv_bfloat16 g_xl[(size_t)NROWS * DIM];
__device__ __nv_bfloat16 g_wh[(size_t)DIM * DIM];
__device__ __nv_bfloat16 g_wl[(size_t)DIM * DIM];
// transposed splits of X (view [131072,512] -> store [512][131072])
__device__ __nv_bfloat16 g_xth[(size_t)BLK * NX];
__device__ __nv_bfloat16 g_xtl[(size_t)BLK * NX];

// symmetric gram tile pairs (lower triangle, 10 of 16)
__constant__ int c_pa[10] = {0,1,1,2,2,2,3,3,3,3};
__constant__ int c_pb[10] = {0,0,1,0,1,2,0,1,2,3};

// ---------------- PTX helpers (sm_80+ features only) ----------------
__device__ __forceinline__ uint32_t smem_u32(const void* p) {
    uint32_t a;
    asm("{ .reg .u64 t; cvta.to.shared.u64 t, %1; cvt.u32.u64 %0, t; }" : "=r"(a) : "l"(p));
    return a;
}
__device__ __forceinline__ void cp16(uint32_t d, const void* s) {
    asm volatile("cp.async.cg.shared.global [%0], [%1], 16;" :: "r"(d), "l"(s));
}
__device__ __forceinline__ void cp_commit() { asm volatile("cp.async.commit_group;"); }
__device__ __forceinline__ void cp_wait0()  { asm volatile("cp.async.wait_group 0;"); }
__device__ __forceinline__ void cp_wait1()  { asm volatile("cp.async.wait_group 1;"); }

__device__ __forceinline__ void ldsm4(uint32_t& r0, uint32_t& r1, uint32_t& r2, uint32_t& r3, uint32_t a) {
    asm volatile("ldmatrix.sync.aligned.m8n8.x4.shared.b16 {%0,%1,%2,%3}, [%4];"
                 : "=r"(r0), "=r"(r1), "=r"(r2), "=r"(r3) : "r"(a));
}
__device__ __forceinline__ void mma16816bf(float* c, const uint32_t* a, uint32_t b0, uint32_t b1) {
    asm volatile("mma.sync.aligned.m16n8k16.row.col.f32.bf16.bf16.f32 "
                 "{%0,%1,%2,%3}, {%4,%5,%6,%7}, {%8,%9}, {%0,%1,%2,%3};"
                 : "+f"(c[0]), "+f"(c[1]), "+f"(c[2]), "+f"(c[3])
                 : "r"(a[0]), "r"(a[1]), "r"(a[2]), "r"(a[3]), "r"(b0), "r"(b1));
}

// ---------------- zero accumulators ----------------
__global__ void zero_kernel() {
    int idx = blockIdx.x * blockDim.x + threadIdx.x;
    int total = BLK * BLK + BLK + 1;
    for (int i = idx; i < total; i += gridDim.x * blockDim.x) {
        if (i < BLK * BLK) g_G[i] = 0.0f;
        else if (i < BLK * BLK + BLK) g_meanAcc[i - BLK * BLK] = 0.0f;
        else g_normSq = 0.0f;
    }
}

// ---------------- fused: bf16 hi/lo split of x (row-major) + column sums ----------------
// 256 blocks x 512 threads; thread t owns column t over 512 rows.
__global__ void __launch_bounds__(512) split_x_mean_kernel(const float* __restrict__ x) {
    const int t = threadIdx.x;
    const size_t base = (size_t)blockIdx.x * 512 * BLK;
    float s = 0.0f;
    #pragma unroll 4
    for (int r = 0; r < 512; r++) {
        size_t idx = base + (size_t)r * BLK + t;
        float v = x[idx];
        __nv_bfloat16 h = __float2bfloat16(v);
        __nv_bfloat16 l = __float2bfloat16(v - __bfloat162float(h));
        g_xh[idx] = h;
        g_xl[idx] = l;
        s += v;
    }
    atomicAdd(&g_meanAcc[t], s);
}

// ---------------- bf16 hi/lo split of folded weight ----------------
__global__ void split_w_kernel() {
    size_t i = ((size_t)blockIdx.x * 256 + threadIdx.x) * 4;
    float4 v = *(const float4*)(g_Wf + i);
    __nv_bfloat16 h0 = __float2bfloat16(v.x), h1 = __float2bfloat16(v.y);
    __nv_bfloat16 h2 = __float2bfloat16(v.z), h3 = __float2bfloat16(v.w);
    __nv_bfloat16 l0 = __float2bfloat16(v.x - __bfloat162float(h0));
    __nv_bfloat16 l1 = __float2bfloat16(v.y - __bfloat162float(h1));
    __nv_bfloat16 l2 = __float2bfloat16(v.z - __bfloat162float(h2));
    __nv_bfloat16 l3 = __float2bfloat16(v.w - __bfloat162float(h3));
    *(__nv_bfloat162*)(g_wh + i)     = __halves2bfloat162(h0, h1);
    *(__nv_bfloat162*)(g_wh + i + 2) = __halves2bfloat162(h2, h3);
    *(__nv_bfloat162*)(g_wl + i)     = __halves2bfloat162(l0, l1);
    *(__nv_bfloat162*)(g_wl + i + 2) = __halves2bfloat162(l2, l3);
}

// ---------------- transposed bf16 hi/lo split: X[131072][512] -> xt[512][131072] ----------------
__global__ void __launch_bounds__(256) split_xt_kernel(const float* __restrict__ x) {
    __shared__ float tile[64][65];
    const int tid = threadIdx.x;
    const int r0 = blockIdx.x * 64;
    const int c0 = blockIdx.y * 64;
    #pragma unroll
    for (int i = 0; i < 4; i++) {
        int r = i * 16 + (tid >> 4);
        int c = (tid & 15) * 4;
        float4 v = *(const float4*)(x + (size_t)(r0 + r) * BLK + c0 + c);
        tile[r][c] = v.x; tile[r][c + 1] = v.y; tile[r][c + 2] = v.z; tile[r][c + 3] = v.w;
    }
    __syncthreads();
    #pragma unroll
    for (int i = 0; i < 4; i++) {
        int cc = i * 16 + (tid >> 4);
        int r = (tid & 15) * 4;
        float v0 = tile[r][cc], v1 = tile[r + 1][cc], v2 = tile[r + 2][cc], v3 = tile[r + 3][cc];
        __nv_bfloat16 h0 = __float2bfloat16(v0), h1 = __float2bfloat16(v1);
        __nv_bfloat16 h2 = __float2bfloat16(v2), h3 = __float2bfloat16(v3);
        __nv_bfloat16 l0 = __float2bfloat16(v0 - __bfloat162float(h0));
        __nv_bfloat16 l1 = __float2bfloat16(v1 - __bfloat162float(h1));
        __nv_bfloat16 l2 = __float2bfloat16(v2 - __bfloat162float(h2));
        __nv_bfloat16 l3 = __float2bfloat16(v3 - __bfloat162float(h3));
        size_t o = (size_t)(c0 + cc) * NX + r0 + r;
        *(__nv_bfloat162*)(g_xth + o)     = __halves2bfloat162(h0, h1);
        *(__nv_bfloat162*)(g_xth + o + 2) = __halves2bfloat162(h2, h3);
        *(__nv_bfloat162*)(g_xtl + o)     = __halves2bfloat162(l0, l1);
        *(__nv_bfloat162*)(g_xtl + o + 2) = __halves2bfloat162(l2, l3);
    }
}

__global__ void mean_scale_kernel() {
    int t = threadIdx.x;
    g_mean[t] = g_meanAcc[t] * (1.0f / (float)NX);
}

// ============ MMA tile machinery: BK=32, 64B rows, 4-chunk XOR swizzle ============
#define OSTG 32768

// ---------------- gram via mma bf16x3 ----------------
__device__ __forceinline__ void load_stage_gram(uint32_t sbase, int a0, int b0, int k0, int tid) {
    #pragma unroll
    for (int i = 0; i < 8; i++) {
        int q = tid + i * 256;
        int op = q >> 9, rem = q & 511;
        int r = rem >> 2, c = rem & 3;
        uint32_t dst = sbase + (uint32_t)op * 8192u + (uint32_t)(r * 64) + (uint32_t)((c ^ ((r >> 1) & 3)) * 16);
        const __nv_bfloat16* src;
        if (op == 0)      src = g_xth + (size_t)(a0 + r) * NX + k0 + c * 8;
        else if (op == 1) src = g_xtl + (size_t)(a0 + r) * NX + k0 + c * 8;
        else if (op == 2) src = g_xth + (size_t)(b0 + r) * NX + k0 + c * 8;
        else              src = g_xtl + (size_t)(b0 + r) * NX + k0 + c * 8;
        cp16(dst, src);
    }
}

__global__ void __launch_bounds__(256, 2) gram_mma(int dummy) {
    extern __shared__ __align__(16) char dsm[];
    const uint32_t sb = smem_u32(dsm);
    const int tid = threadIdx.x, lane = tid & 31, wid = tid >> 5;
    const int a0 = c_pa[blockIdx.x] * 128;
    const int b0 = c_pb[blockIdx.x] * 128;
    const int kbase = blockIdx.y * 2048;
    const int wm = wid & 1, wn = wid >> 1;

    float c[4][4][4];
    #pragma unroll
    for (int mf = 0; mf < 4; mf++)
        #pragma unroll
        for (int nf = 0; nf < 4; nf++)
            #pragma unroll
            for (int r = 0; r < 4; r++) c[mf][nf][r] = 0.0f;

    load_stage_gram(sb,        a0, b0, kbase,      tid); cp_commit();
    load_stage_gram(sb + OSTG, a0, b0, kbase + 32, tid); cp_commit();

    const int a_row  = wm * 64 + (lane & 15);
    const int a_kc   = (lane >> 4) & 1;
    const int b_row4 = wn * 32 + (lane & 7) + ((lane >> 4) << 3);   // +8 for lanes 16-31
    const int b_kpar = (lane >> 3) & 1;                             // chunk parity

    int cs = 0, ls = 2;
    for (int it = 0; it < 64; it++) {
        cp_wait1();
        __syncthreads();
        int pf = it + 2; if (pf > 63) pf = 63;
        load_stage_gram(sb + (uint32_t)ls * OSTG, a0, b0, kbase + pf * 32, tid);
        cp_commit();
        const uint32_t sa = sb + (uint32_t)cs * OSTG;

        #pragma unroll
        for (int s2 = 0; s2 < 2; s2++) {
            uint32_t ah[4][4], al[4][4];
            #pragma unroll
            for (int mf = 0; mf < 4; mf++) {
                int r = a_row + mf * 16;
                uint32_t addr = sa + (uint32_t)(r * 64) +
                                (uint32_t)((((s2 << 1) | a_kc) ^ ((r >> 1) & 3)) * 16);
                ldsm4(ah[mf][0], ah[mf][1], ah[mf][2], ah[mf][3], addr);
                ldsm4(al[mf][0], al[mf][1], al[mf][2], al[mf][3], addr + 8192u);
            }
            #pragma unroll
            for (int np = 0; np < 2; np++) {
                int r = b_row4 + np * 16;
                uint32_t base = (uint32_t)(r * 64) +
                                (uint32_t)((((s2 << 1) | b_kpar) ^ ((r >> 1) & 3)) * 16);
                uint32_t bh0, bh1, bh2, bh3, bl0, bl1, bl2, bl3;
                ldsm4(bh0, bh1, bh2, bh3, sa + 16384u + base);
                ldsm4(bl0, bl1, bl2, bl3, sa + 24576u + base);
                #pragma unroll
                for (int mf = 0; mf < 4; mf++) {
                    mma16816bf(c[mf][2 * np],     ah[mf], bh0, bh1);
                    mma16816bf(c[mf][2 * np],     ah[mf], bl0, bl1);
                    mma16816bf(c[mf][2 * np],     al[mf], bh0, bh1);
                    mma16816bf(c[mf][2 * np + 1], ah[mf], bh2, bh3);
                    mma16816bf(c[mf][2 * np + 1], ah[mf], bl2, bl3);
                    mma16816bf(c[mf][2 * np + 1], al[mf], bh2, bh3);
                }
            }
        }
        cs = (cs == 2) ? 0 : cs + 1;
        ls = (ls == 2) ? 0 : ls + 1;
    }
    cp_wait0();

    #pragma unroll
    for (int mf = 0; mf < 4; mf++) {
        int r0 = a0 + wm * 64 + mf * 16 + (lane >> 2);
        #pragma unroll
        for (int nf = 0; nf < 4; nf++) {
            int cb = b0 + wn * 32 + nf * 8 + (lane & 3) * 2;
            atomicAdd(&g_G[r0 * BLK + cb],           c[mf][nf][0]);
            atomicAdd(&g_G[r0 * BLK + cb + 1],       c[mf][nf][1]);
            atomicAdd(&g_G[(r0 + 8) * BLK + cb],     c[mf][nf][2]);
            atomicAdd(&g_G[(r0 + 8) * BLK + cb + 1], c[mf][nf][3]);
        }
    }
}

// ---------------- cov = G/n - m m^T + eps I (mirror upper from lower) ----------------
__global__ void cov_kernel() {
    int idx = blockIdx.x * blockDim.x + threadIdx.x;
    int a = idx >> 9, b = idx & 511;
    float graw = (a >= b) ? g_G[a * BLK + b] : g_G[b * BLK + a];
    float c = graw * (1.0f / (float)NX) - g_mean[a] * g_mean[b] + (a == b ? EPSV : 0.0f);
    g_C[idx] = c;
    float v = c * c;
    #pragma unroll
    for (int o = 16; o > 0; o >>= 1) v += __shfl_xor_sync(0xffffffffu, v, o);
    __shared__ float ws[8];
    int lane = threadIdx.x & 31, w = threadIdx.x >> 5;
    if (lane == 0) ws[w] = v;
    __syncthreads();
    if (w == 0) {
        float t = (lane < 8) ? ws[lane] : 0.0f;
        #pragma unroll
        for (int o = 4; o > 0; o >>= 1) t += __shfl_xor_sync(0xffffffffu, t, o);
        if (lane == 0) atomicAdd(&g_normSq, t);
    }
}

__global__ void scalars_kernel() {
    float norm = sqrtf(g_normSq);
    g_invNorm = 1.0f / norm;
    g_zscale = rsqrtf(norm);
}

__global__ void init_yz_kernel() {
    int idx = blockIdx.x * blockDim.x + threadIdx.x;
    int a = idx >> 9, b = idx & 511;
    g_Y[0][idx] = g_C[idx] * g_invNorm;
    g_Z[0][idx] = (a == b) ? 1.0f : 0.0f;
}

// ---------------- 512x512x512 GEMM core (SIMT, 64x64 tile) ----------------
__device__ __forceinline__ void mm512_tile(const float* __restrict__ A,
                                           const float* __restrict__ B,
                                           int m0, int n0, float acc[4][4]) {
    __shared__ float As[16][68];
    __shared__ float Bs[16][68];
    const int tid = threadIdx.x;
    const int tx = tid & 15, ty = tid >> 4;
    for (int k0 = 0; k0 < 512; k0 += 16) {
        #pragma unroll
        for (int i = 0; i < 4; i++) {
            int l = tid + i * 256;
            int m = l >> 4, k = l & 15;
            As[k][m] = A[(m0 + m) * 512 + k0 + k];
            int kb = l >> 6, n = l & 63;
            Bs[kb][n] = B[(k0 + kb) * 512 + n0 + n];
        }
        __syncthreads();
        #pragma unroll
        for (int k = 0; k < 16; k++) {
            float a[4], b[4];
            *(float4*)a = *(const float4*)&As[k][ty * 4];
            *(float4*)b = *(const float4*)&Bs[k][tx * 4];
            #pragma unroll
            for (int i = 0; i < 4; i++)
                #pragma unroll
                for (int j = 0; j < 4; j++) acc[i][j] += a[i] * b[j];
        }
        __syncthreads();
    }
}

__global__ void __launch_bounds__(256) ns_T_kernel(int cur) {
    const float* A = g_Z[cur];
    const float* B = g_Y[cur];
    int m0 = blockIdx.y * 64, n0 = blockIdx.x * 64;
    float acc[4][4] = {};
    mm512_tile(A, B, m0, n0, acc);
    int tx = threadIdx.x & 15, ty = threadIdx.x >> 4;
    #pragma unroll
    for (int i = 0; i < 4; i++)
        #pragma unroll
        for (int j = 0; j < 4; j++) {
            int r = m0 + ty * 4 + i, c = n0 + tx * 4 + j;
            g_T[r * 512 + c] = (r == c ? 1.5f : 0.0f) - 0.5f * acc[i][j];
        }
}

__global__ void __launch_bounds__(256) ns_pair_kernel(int cur) {
    const float* A; const float* B; float* C;
    if (blockIdx.z == 0) { A = g_Y[cur]; B = g_T; C = g_Y[cur ^ 1]; }
    else                 { A = g_T; B = g_Z[cur]; C = g_Z[cur ^ 1]; }
    int m0 = blockIdx.y * 64, n0 = blockIdx.x * 64;
    float acc[4][4] = {};
    mm512_tile(A, B, m0, n0, acc);
    int tx = threadIdx.x & 15, ty = threadIdx.x >> 4;
    #pragma unroll
    for (int i = 0; i < 4; i++)
        #pragma unroll
        for (int j = 0; j < 4; j++)
            C[(m0 + ty * 4 + i) * 512 + n0 + tx * 4 + j] = acc[i][j];
}

// ---------------- fold: Wf = (weight.reshape(8192,512) @ Zfinal) * zscale ----------------
__global__ void __launch_bounds__(256) fold_kernel(const float* __restrict__ W, int zfin) {
    __shared__ float As[16][132];
    __shared__ float Bs[16][132];
    const float* Zf = g_Z[zfin];
    const int n0 = blockIdx.x * 128;
    const int m0 = blockIdx.y * 128;
    const int tid = threadIdx.x;
    const int tx = tid & 15, ty = tid >> 4;
    float acc[8][8];
    #pragma unroll
    for (int i = 0; i < 8; i++)
        #pragma unroll
        for (int j = 0; j < 8; j++) acc[i][j] = 0.0f;

    for (int k0 = 0; k0 < 512; k0 += 16) {
        #pragma unroll
        for (int i = 0; i < 8; i++) {
            int l = tid + i * 256;
            int r = l >> 4, k = l & 15;
            As[k][r] = W[(m0 + r) * 512 + k0 + k];
            int kb = l >> 7, c = l & 127;
            Bs[kb][c] = Zf[(k0 + kb) * 512 + n0 + c];
        }
        __syncthreads();
        #pragma unroll
        for (int k = 0; k < 16; k++) {
            float a[8], b[8];
            *(float4*)(a)     = *(const float4*)&As[k][ty * 8];
            *(float4*)(a + 4) = *(const float4*)&As[k][ty * 8 + 4];
            *(float4*)(b)     = *(const float4*)&Bs[k][tx * 8];
            *(float4*)(b + 4) = *(const float4*)&Bs[k][tx * 8 + 4];
            #pragma unroll
            for (int i = 0; i < 8; i++)
                #pragma unroll
                for (int j = 0; j < 8; j++) acc[i][j] += a[i] * b[j];
        }
        __syncthreads();
    }
    float s = g_zscale;
    #pragma unroll
    for (int i = 0; i < 8; i++)
        #pragma unroll
        for (int j = 0; j < 8; j++)
            g_Wf[(m0 + ty * 8 + i) * 512 + n0 + tx * 8 + j] = acc[i][j] * s;
}

// ---------------- b_eff ----------------
__global__ void bias_kernel(const float* __restrict__ bias) {
    int o = blockIdx.x;
    int t = threadIdx.x;
    float s = 0.0f;
    for (int k = t; k < DIM; k += 256)
        s += g_Wf[o * DIM + k] * g_mean[k & 511];
    #pragma unroll
    for (int off = 16; off > 0; off >>= 1) s += __shfl_xor_sync(0xffffffffu, s, off);
    __shared__ float ws[8];
    int lane = t & 31, w = t >> 5;
    if (lane == 0) ws[w] = s;
    __syncthreads();
    if (t == 0) {
        float tot = 0.0f;
        #pragma unroll
        for (int i = 0; i < 8; i++) tot += ws[i];
        g_beff[o] = bias[o] - tot;
    }
}

// ---------------- main GEMM via mma bf16x3 (3-stage, BK=32, 2 CTAs/SM) ----------------
__device__ __forceinline__ void load_stage_out(uint32_t sbase, int m0, int n0, int k0, int tid) {
    #pragma unroll
    for (int i = 0; i < 8; i++) {
        int q = tid + i * 256;
        int op = q >> 9, rem = q & 511;
        int r = rem >> 2, c = rem & 3;
        uint32_t dst = sbase + (uint32_t)op * 8192u + (uint32_t)(r * 64) + (uint32_t)((c ^ ((r >> 1) & 3)) * 16);
        const __nv_bfloat16* src;
        if (op == 0)      src = g_xh + (size_t)(m0 + r) * DIM + k0 + c * 8;
        else if (op == 1) src = g_xl + (size_t)(m0 + r) * DIM + k0 + c * 8;
        else if (op == 2) src = g_wh + (size_t)(n0 + r) * DIM + k0 + c * 8;
        else              src = g_wl + (size_t)(n0 + r) * DIM + k0 + c * 8;
        cp16(dst, src);
    }
}

__global__ void __launch_bounds__(256, 2) out_gemm_mma(float* __restrict__ out) {
    extern __shared__ __align__(16) char dsm[];
    const uint32_t sb = smem_u32(dsm);
    float* sbias = (float*)(dsm + 3 * OSTG);
    const int tid = threadIdx.x, lane = tid & 31, wid = tid >> 5;
    const int n0 = blockIdx.x * 128, m0 = blockIdx.y * 128;
    const int wm = wid & 1, wn = wid >> 1;

    if (tid < 128) sbias[tid] = g_beff[n0 + tid];

    float c[4][4][4];
    #pragma unroll
    for (int mf = 0; mf < 4; mf++)
        #pragma unroll
        for (int nf = 0; nf < 4; nf++)
            #pragma unroll
            for (int r = 0; r < 4; r++) c[mf][nf][r] = 0.0f;

    load_stage_out(sb,        m0, n0, 0,  tid); cp_commit();
    load_stage_out(sb + OSTG, m0, n0, 32, tid); cp_commit();

    const int a_row  = wm * 64 + (lane & 15);
    const int a_kc   = (lane >> 4) & 1;
    const int b_row4 = wn * 32 + (lane & 7) + ((lane >> 4) << 3);
    const int b_kpar = (lane >> 3) & 1;

    int cs = 0, ls = 2;
    for (int it = 0; it < 64; it++) {
        cp_wait1();
        __syncthreads();
        int pf = it + 2; if (pf > 63) pf = 63;
        load_stage_out(sb + (uint32_t)ls * OSTG, m0, n0, pf * 32, tid);
        cp_commit();
        const uint32_t sa = sb + (uint32_t)cs * OSTG;

        #pragma unroll
        for (int s2 = 0; s2 < 2; s2++) {
            uint32_t ah[4][4], al[4][4];
            #pragma unroll
            for (int mf = 0; mf < 4; mf++) {
                int r = a_row + mf * 16;
                uint32_t addr = sa + (uint32_t)(r * 64) +
                                (uint32_t)((((s2 << 1) | a_kc) ^ ((r >> 1) & 3)) * 16);
                ldsm4(ah[mf][0], ah[mf][1], ah[mf][2], ah[mf][3], addr);
                ldsm4(al[mf][0], al[mf][1], al[mf][2], al[mf][3], addr + 8192u);
            }
            #pragma unroll
            for (int np = 0; np < 2; np++) {
                int r = b_row4 + np * 16;
                uint32_t base = (uint32_t)(r * 64) +
                                (uint32_t)((((s2 << 1) | b_kpar) ^ ((r >> 1) & 3)) * 16);
                uint32_t bh0, bh1, bh2, bh3, bl0, bl1, bl2, bl3;
                ldsm4(bh0, bh1, bh2, bh3, sa + 16384u + base);
                ldsm4(bl0, bl1, bl2, bl3, sa + 24576u + base);
                #pragma unroll
                for (int mf = 0; mf < 4; mf++) {
                    mma16816bf(c[mf][2 * np],     ah[mf], bh0, bh1);
                    mma16816bf(c[mf][2 * np],     ah[mf], bl0, bl1);
                    mma16816bf(c[mf][2 * np],     al[mf], bh0, bh1);
                    mma16816bf(c[mf][2 * np + 1], ah[mf], bh2, bh3);
                    mma16816bf(c[mf][2 * np + 1], ah[mf], bl2, bl3);
                    mma16816bf(c[mf][2 * np + 1], al[mf], bh2, bh3);
                }
            }
        }
        cs = (cs == 2) ? 0 : cs + 1;
        ls = (ls == 2) ? 0 : ls + 1;
    }
    cp_wait0();

    #pragma unroll
    for (int mf = 0; mf < 4; mf++) {
        int r0 = m0 + wm * 64 + mf * 16 + (lane >> 2);
        #pragma unroll
        for (int nf = 0; nf < 4; nf++) {
            int cb = wn * 32 + nf * 8 + (lane & 3) * 2;
            float2 v0, v1;
            v0.x = c[mf][nf][0] + sbias[cb];
            v0.y = c[mf][nf][1] + sbias[cb + 1];
            v1.x = c[mf][nf][2] + sbias[cb];
            v1.y = c[mf][nf][3] + sbias[cb + 1];
            *(float2*)&out[(size_t)r0 * DIM + n0 + cb] = v0;
            *(float2*)&out[(size_t)(r0 + 8) * DIM + n0 + cb] = v1;
        }
    }
}

// ---------------- host orchestration ----------------
extern "C" void kernel_launch(void* const* d_in, const int* in_sizes, int n_in,
                              void* d_out, int out_size) {
    const float* x      = (const float*)d_in[0];
    const float* weight = (const float*)d_in[1];
    const float* bias   = (const float*)d_in[2];
    float* out          = (float*)d_out;

    cudaFuncSetAttribute(gram_mma,     cudaFuncAttributeMaxDynamicSharedMemorySize, 3 * OSTG);
    cudaFuncSetAttribute(out_gemm_mma, cudaFuncAttributeMaxDynamicSharedMemorySize, 3 * OSTG + 512);

    zero_kernel<<<1026, 256>>>();
    split_x_mean_kernel<<<256, 512>>>(x);
    split_xt_kernel<<<dim3(2048, 8), 256>>>(x);
    mean_scale_kernel<<<1, 512>>>();
    gram_mma<<<dim3(10, 64), 256, 3 * OSTG>>>(0);
    cov_kernel<<<1024, 256>>>();
    scalars_kernel<<<1, 1>>>();
    init_yz_kernel<<<1024, 256>>>();

    int cur = 0;
    for (int it = 0; it < NITER; it++) {
        ns_T_kernel<<<dim3(8, 8), 256>>>(cur);
        ns_pair_kernel<<<dim3(8, 8, 2), 256>>>(cur);
        cur ^= 1;
    }

    fold_kernel<<<dim3(4, 64), 256>>>(weight, cur);
    bias_kernel<<<DIM, 256>>>(bias);
    split_w_kernel<<<4096, 256>>>();

    out_gemm_mma<<<dim3(16, 256), 256, 3 * OSTG + 512>>>(out);
}

// round 16
// speedup vs baseline: 1.1860x; 1.0323x over previous
#include <cuda_runtime.h>
#include <cuda_bf16.h>
#include <math.h>
#include <stdint.h>

// Problem constants
#define NROWS 32768
#define DIM   2048
#define BLK   512
#define NX    (NROWS * DIM / BLK)   // 131072 rows of X
#define EPSV  1e-5f
#define NITER 5

// ---------------- device scratch (no allocations allowed) ----------------
__device__ float g_meanAcc[BLK];
__device__ float g_mean[BLK];
__device__ float g_G[BLK * BLK];
__device__ float g_C[BLK * BLK];
__device__ float g_Y[2][BLK * BLK];
__device__ float g_Z[2][BLK * BLK];
__device__ float g_T[BLK * BLK];
__device__ float g_normSq;
__device__ float g_invNorm;
__device__ float g_zscale;
__device__ float g_Wf[DIM * DIM];      // folded weight fp32
__device__ float g_beff[DIM];

// bf16 hi/lo splits (row-major only; gram transposes at load via ldmatrix.trans)
__device__ __nv_bfloat16 g_xh[(size_t)NROWS * DIM];
__device__ __nv_bfloat16 g_xl[(size_t)NROWS * DIM];
__device__ __nv_bfloat16 g_wh[(size_t)DIM * DIM];
__device__ __nv_bfloat16 g_wl[(size_t)DIM * DIM];

// symmetric gram tile pairs (lower triangle, 10 of 16)
__constant__ int c_pa[10] = {0,1,1,2,2,2,3,3,3,3};
__constant__ int c_pb[10] = {0,0,1,0,1,2,0,1,2,3};

// ---------------- PTX helpers (sm_80+ features only) ----------------
__device__ __forceinline__ uint32_t smem_u32(const void* p) {
    uint32_t a;
    asm("{ .reg .u64 t; cvta.to.shared.u64 t, %1; cvt.u32.u64 %0, t; }" : "=r"(a) : "l"(p));
    return a;
}
__device__ __forceinline__ void cp16(uint32_t d, const void* s) {
    asm volatile("cp.async.cg.shared.global [%0], [%1], 16;" :: "r"(d), "l"(s));
}
__device__ __forceinline__ void cp_commit() { asm volatile("cp.async.commit_group;"); }
__device__ __forceinline__ void cp_wait0()  { asm volatile("cp.async.wait_group 0;"); }
__device__ __forceinline__ void cp_wait1()  { asm volatile("cp.async.wait_group 1;"); }

__device__ __forceinline__ void ldsm4(uint32_t& r0, uint32_t& r1, uint32_t& r2, uint32_t& r3, uint32_t a) {
    asm volatile("ldmatrix.sync.aligned.m8n8.x4.shared.b16 {%0,%1,%2,%3}, [%4];"
                 : "=r"(r0), "=r"(r1), "=r"(r2), "=r"(r3) : "r"(a));
}
__device__ __forceinline__ void ldsm4t(uint32_t& r0, uint32_t& r1, uint32_t& r2, uint32_t& r3, uint32_t a) {
    asm volatile("ldmatrix.sync.aligned.m8n8.x4.trans.shared.b16 {%0,%1,%2,%3}, [%4];"
                 : "=r"(r0), "=r"(r1), "=r"(r2), "=r"(r3) : "r"(a));
}
__device__ __forceinline__ void mma16816bf(float* c, const uint32_t* a, uint32_t b0, uint32_t b1) {
    asm volatile("mma.sync.aligned.m16n8k16.row.col.f32.bf16.bf16.f32 "
                 "{%0,%1,%2,%3}, {%4,%5,%6,%7}, {%8,%9}, {%0,%1,%2,%3};"
                 : "+f"(c[0]), "+f"(c[1]), "+f"(c[2]), "+f"(c[3])
                 : "r"(a[0]), "r"(a[1]), "r"(a[2]), "r"(a[3]), "r"(b0), "r"(b1));
}

// ---------------- zero accumulators ----------------
__global__ void zero_kernel() {
    int idx = blockIdx.x * blockDim.x + threadIdx.x;
    int total = BLK * BLK + BLK + 1;
    for (int i = idx; i < total; i += gridDim.x * blockDim.x) {
        if (i < BLK * BLK) g_G[i] = 0.0f;
        else if (i < BLK * BLK + BLK) g_meanAcc[i - BLK * BLK] = 0.0f;
        else g_normSq = 0.0f;
    }
}

// ---------------- fused: bf16 hi/lo split of x (row-major) + column sums ----------------
__global__ void __launch_bounds__(512) split_x_mean_kernel(const float* __restrict__ x) {
    const int t = threadIdx.x;
    const size_t base = (size_t)blockIdx.x * 512 * BLK;
    float s = 0.0f;
    #pragma unroll 4
    for (int r = 0; r < 512; r++) {
        size_t idx = base + (size_t)r * BLK + t;
        float v = x[idx];
        __nv_bfloat16 h = __float2bfloat16(v);
        __nv_bfloat16 l = __float2bfloat16(v - __bfloat162float(h));
        g_xh[idx] = h;
        g_xl[idx] = l;
        s += v;
    }
    atomicAdd(&g_meanAcc[t], s);
}

// ---------------- bf16 hi/lo split of folded weight ----------------
__global__ void split_w_kernel() {
    size_t i = ((size_t)blockIdx.x * 256 + threadIdx.x) * 4;
    float4 v = *(const float4*)(g_Wf + i);
    __nv_bfloat16 h0 = __float2bfloat16(v.x), h1 = __float2bfloat16(v.y);
    __nv_bfloat16 h2 = __float2bfloat16(v.z), h3 = __float2bfloat16(v.w);
    __nv_bfloat16 l0 = __float2bfloat16(v.x - __bfloat162float(h0));
    __nv_bfloat16 l1 = __float2bfloat16(v.y - __bfloat162float(h1));
    __nv_bfloat16 l2 = __float2bfloat16(v.z - __bfloat162float(h2));
    __nv_bfloat16 l3 = __float2bfloat16(v.w - __bfloat162float(h3));
    *(__nv_bfloat162*)(g_wh + i)     = __halves2bfloat162(h0, h1);
    *(__nv_bfloat162*)(g_wh + i + 2) = __halves2bfloat162(h2, h3);
    *(__nv_bfloat162*)(g_wl + i)     = __halves2bfloat162(l0, l1);
    *(__nv_bfloat162*)(g_wl + i + 2) = __halves2bfloat162(l2, l3);
}

__global__ void mean_scale_kernel() {
    int t = threadIdx.x;
    g_mean[t] = g_meanAcc[t] * (1.0f / (float)NX);
}

// ============ MMA tile machinery ============
#define OSTG 32768

// ---------------- gram via mma bf16x3 with ldmatrix.trans (reads row-major splits) ----------------
// stage: 4 op tiles (A_hi, A_lo, B_hi, B_lo), each 32 k-rows x 256B (128 cols bf16) = 8KB
// swizzle: 16B chunk c within a row stored at c ^ (row & 7)
__device__ __forceinline__ void load_stage_gram(uint32_t sbase, int a0, int b0, int k0, int tid) {
    #pragma unroll
    for (int i = 0; i < 8; i++) {
        int q = tid + i * 256;
        int op = q >> 9, rem = q & 511;
        int r = rem >> 4;          // k-row 0..31
        int c = rem & 15;          // 16B chunk 0..15 (col dim)
        uint32_t dst = sbase + (uint32_t)op * 8192u + (uint32_t)(r * 256) + (uint32_t)((c ^ (r & 7)) * 16);
        int col = ((op < 2) ? a0 : b0) + c * 8;
        const __nv_bfloat16* buf = (op & 1) ? g_xl : g_xh;
        cp16(dst, buf + (size_t)(k0 + r) * BLK + col);
    }
}

__global__ void __launch_bounds__(256, 2) gram_mma(int dummy) {
    extern __shared__ __align__(16) char dsm[];
    const uint32_t sb = smem_u32(dsm);
    const int tid = threadIdx.x, lane = tid & 31, wid = tid >> 5;
    const int a0 = c_pa[blockIdx.x] * 128;
    const int b0 = c_pb[blockIdx.x] * 128;
    const int kbase = blockIdx.y * 2048;
    const int wm = wid & 1, wn = wid >> 1;

    float c[4][4][4];
    #pragma unroll
    for (int mf = 0; mf < 4; mf++)
        #pragma unroll
        for (int nf = 0; nf < 4; nf++)
            #pragma unroll
            for (int r = 0; r < 4; r++) c[mf][nf][r] = 0.0f;

    load_stage_gram(sb,        a0, b0, kbase,      tid); cp_commit();
    load_stage_gram(sb + OSTG, a0, b0, kbase + 32, tid); cp_commit();

    // trans-ldmatrix lane maps
    const int a_k    = (lane & 7) + ((lane >> 4) << 3);
    const int a_moff = ((lane >> 3) & 1) * 8;
    const int b_k    = (lane & 7) + (((lane >> 3) & 1) << 3);
    const int b_noff = ((lane >> 4) & 1) * 8;

    int cs = 0, ls = 2;
    for (int it = 0; it < 64; it++) {
        cp_wait1();
        __syncthreads();
        int pf = it + 2; if (pf > 63) pf = 63;
        load_stage_gram(sb + (uint32_t)ls * OSTG, a0, b0, kbase + pf * 32, tid);
        cp_commit();
        const uint32_t sa = sb + (uint32_t)cs * OSTG;

        #pragma unroll
        for (int s2 = 0; s2 < 2; s2++) {
            const int ak = a_k + s2 * 16;
            const int bk = b_k + s2 * 16;
            uint32_t ah[4][4], al[4][4];
            #pragma unroll
            for (int mf = 0; mf < 4; mf++) {
                int m_local = wm * 64 + mf * 16 + a_moff;
                int chunk = m_local >> 3;
                uint32_t addr = sa + (uint32_t)(ak * 256) + (uint32_t)((chunk ^ (ak & 7)) * 16);
                ldsm4t(ah[mf][0], ah[mf][1], ah[mf][2], ah[mf][3], addr);
                ldsm4t(al[mf][0], al[mf][1], al[mf][2], al[mf][3], addr + 8192u);
            }
            #pragma unroll
            for (int np = 0; np < 2; np++) {
                int n_local = wn * 32 + np * 16 + b_noff;
                int chunk = n_local >> 3;
                uint32_t addr = sa + 16384u + (uint32_t)(bk * 256) + (uint32_t)((chunk ^ (bk & 7)) * 16);
                uint32_t bh0, bh1, bh2, bh3, bl0, bl1, bl2, bl3;
                ldsm4t(bh0, bh1, bh2, bh3, addr);
                ldsm4t(bl0, bl1, bl2, bl3, addr + 8192u);
                #pragma unroll
                for (int mf = 0; mf < 4; mf++) {
                    mma16816bf(c[mf][2 * np],     ah[mf], bh0, bh1);
                    mma16816bf(c[mf][2 * np],     ah[mf], bl0, bl1);
                    mma16816bf(c[mf][2 * np],     al[mf], bh0, bh1);
                    mma16816bf(c[mf][2 * np + 1], ah[mf], bh2, bh3);
                    mma16816bf(c[mf][2 * np + 1], ah[mf], bl2, bl3);
                    mma16816bf(c[mf][2 * np + 1], al[mf], bh2, bh3);
                }
            }
        }
        cs = (cs == 2) ? 0 : cs + 1;
        ls = (ls == 2) ? 0 : ls + 1;
    }
    cp_wait0();

    #pragma unroll
    for (int mf = 0; mf < 4; mf++) {
        int r0 = a0 + wm * 64 + mf * 16 + (lane >> 2);
        #pragma unroll
        for (int nf = 0; nf < 4; nf++) {
            int cb = b0 + wn * 32 + nf * 8 + (lane & 3) * 2;
            atomicAdd(&g_G[r0 * BLK + cb],           c[mf][nf][0]);
            atomicAdd(&g_G[r0 * BLK + cb + 1],       c[mf][nf][1]);
            atomicAdd(&g_G[(r0 + 8) * BLK + cb],     c[mf][nf][2]);
            atomicAdd(&g_G[(r0 + 8) * BLK + cb + 1], c[mf][nf][3]);
        }
    }
}

// ---------------- cov = G/n - m m^T + eps I (mirror upper from lower) ----------------
__global__ void cov_kernel() {
    int idx = blockIdx.x * blockDim.x + threadIdx.x;
    int a = idx >> 9, b = idx & 511;
    float graw = (a >= b) ? g_G[a * BLK + b] : g_G[b * BLK + a];
    float c = graw * (1.0f / (float)NX) - g_mean[a] * g_mean[b] + (a == b ? EPSV : 0.0f);
    g_C[idx] = c;
    float v = c * c;
    #pragma unroll
    for (int o = 16; o > 0; o >>= 1) v += __shfl_xor_sync(0xffffffffu, v, o);
    __shared__ float ws[8];
    int lane = threadIdx.x & 31, w = threadIdx.x >> 5;
    if (lane == 0) ws[w] = v;
    __syncthreads();
    if (w == 0) {
        float t = (lane < 8) ? ws[lane] : 0.0f;
        #pragma unroll
        for (int o = 4; o > 0; o >>= 1) t += __shfl_xor_sync(0xffffffffu, t, o);
        if (lane == 0) atomicAdd(&g_normSq, t);
    }
}

__global__ void scalars_kernel() {
    float norm = sqrtf(g_normSq);
    g_invNorm = 1.0f / norm;
    g_zscale = rsqrtf(norm);
}

__global__ void init_yz_kernel() {
    int idx = blockIdx.x * blockDim.x + threadIdx.x;
    int a = idx >> 9, b = idx & 511;
    g_Y[0][idx] = g_C[idx] * g_invNorm;
    g_Z[0][idx] = (a == b) ? 1.0f : 0.0f;
}

// ---------------- 512x512x512 GEMM core (SIMT, 64x64 tile) ----------------
__device__ __forceinline__ void mm512_tile(const float* __restrict__ A,
                                           const float* __restrict__ B,
                                           int m0, int n0, float acc[4][4]) {
    __shared__ float As[16][68];
    __shared__ float Bs[16][68];
    const int tid = threadIdx.x;
    const int tx = tid & 15, ty = tid >> 4;
    for (int k0 = 0; k0 < 512; k0 += 16) {
        #pragma unroll
        for (int i = 0; i < 4; i++) {
            int l = tid + i * 256;
            int m = l >> 4, k = l & 15;
            As[k][m] = A[(m0 + m) * 512 + k0 + k];
            int kb = l >> 6, n = l & 63;
            Bs[kb][n] = B[(k0 + kb) * 512 + n0 + n];
        }
        __syncthreads();
        #pragma unroll
        for (int k = 0; k < 16; k++) {
            float a[4], b[4];
            *(float4*)a = *(const float4*)&As[k][ty * 4];
            *(float4*)b = *(const float4*)&Bs[k][tx * 4];
            #pragma unroll
            for (int i = 0; i < 4; i++)
                #pragma unroll
                for (int j = 0; j < 4; j++) acc[i][j] += a[i] * b[j];
        }
        __syncthreads();
    }
}

__global__ void __launch_bounds__(256) ns_T_kernel(int cur) {
    const float* A = g_Z[cur];
    const float* B = g_Y[cur];
    int m0 = blockIdx.y * 64, n0 = blockIdx.x * 64;
    float acc[4][4] = {};
    mm512_tile(A, B, m0, n0, acc);
    int tx = threadIdx.x & 15, ty = threadIdx.x >> 4;
    #pragma unroll
    for (int i = 0; i < 4; i++)
        #pragma unroll
        for (int j = 0; j < 4; j++) {
            int r = m0 + ty * 4 + i, c = n0 + tx * 4 + j;
            g_T[r * 512 + c] = (r == c ? 1.5f : 0.0f) - 0.5f * acc[i][j];
        }
}

__global__ void __launch_bounds__(256) ns_pair_kernel(int cur) {
    const float* A; const float* B; float* C;
    if (blockIdx.z == 0) { A = g_Y[cur]; B = g_T; C = g_Y[cur ^ 1]; }
    else                 { A = g_T; B = g_Z[cur]; C = g_Z[cur ^ 1]; }
    int m0 = blockIdx.y * 64, n0 = blockIdx.x * 64;
    float acc[4][4] = {};
    mm512_tile(A, B, m0, n0, acc);
    int tx = threadIdx.x & 15, ty = threadIdx.x >> 4;
    #pragma unroll
    for (int i = 0; i < 4; i++)
        #pragma unroll
        for (int j = 0; j < 4; j++)
            C[(m0 + ty * 4 + i) * 512 + n0 + tx * 4 + j] = acc[i][j];
}

// ---------------- fold: Wf = (weight.reshape(8192,512) @ Zfinal) * zscale ----------------
__global__ void __launch_bounds__(256) fold_kernel(const float* __restrict__ W, int zfin) {
    __shared__ float As[16][132];
    __shared__ float Bs[16][132];
    const float* Zf = g_Z[zfin];
    const int n0 = blockIdx.x * 128;
    const int m0 = blockIdx.y * 128;
    const int tid = threadIdx.x;
    const int tx = tid & 15, ty = tid >> 4;
    float acc[8][8];
    #pragma unroll
    for (int i = 0; i < 8; i++)
        #pragma unroll
        for (int j = 0; j < 8; j++) acc[i][j] = 0.0f;

    for (int k0 = 0; k0 < 512; k0 += 16) {
        #pragma unroll
        for (int i = 0; i < 8; i++) {
            int l = tid + i * 256;
            int r = l >> 4, k = l & 15;
            As[k][r] = W[(m0 + r) * 512 + k0 + k];
            int kb = l >> 7, c = l & 127;
            Bs[kb][c] = Zf[(k0 + kb) * 512 + n0 + c];
        }
        __syncthreads();
        #pragma unroll
        for (int k = 0; k < 16; k++) {
            float a[8], b[8];
            *(float4*)(a)     = *(const float4*)&As[k][ty * 8];
            *(float4*)(a + 4) = *(const float4*)&As[k][ty * 8 + 4];
            *(float4*)(b)     = *(const float4*)&Bs[k][tx * 8];
            *(float4*)(b + 4) = *(const float4*)&Bs[k][tx * 8 + 4];
            #pragma unroll
            for (int i = 0; i < 8; i++)
                #pragma unroll
                for (int j = 0; j < 8; j++) acc[i][j] += a[i] * b[j];
        }
        __syncthreads();
    }
    float s = g_zscale;
    #pragma unroll
    for (int i = 0; i < 8; i++)
        #pragma unroll
        for (int j = 0; j < 8; j++)
            g_Wf[(m0 + ty * 8 + i) * 512 + n0 + tx * 8 + j] = acc[i][j] * s;
}

// ---------------- b_eff ----------------
__global__ void bias_kernel(const float* __restrict__ bias) {
    int o = blockIdx.x;
    int t = threadIdx.x;
    float s = 0.0f;
    for (int k = t; k < DIM; k += 256)
        s += g_Wf[o * DIM + k] * g_mean[k & 511];
    #pragma unroll
    for (int off = 16; off > 0; off >>= 1) s += __shfl_xor_sync(0xffffffffu, s, off);
    __shared__ float ws[8];
    int lane = t & 31, w = t >> 5;
    if (lane == 0) ws[w] = s;
    __syncthreads();
    if (t == 0) {
        float tot = 0.0f;
        #pragma unroll
        for (int i = 0; i < 8; i++) tot += ws[i];
        g_beff[o] = bias[o] - tot;
    }
}

// ---------------- main GEMM via mma bf16x3 (3-stage, BK=32, 2 CTAs/SM) ----------------
__device__ __forceinline__ void load_stage_out(uint32_t sbase, int m0, int n0, int k0, int tid) {
    #pragma unroll
    for (int i = 0; i < 8; i++) {
        int q = tid + i * 256;
        int op = q >> 9, rem = q & 511;
        int r = rem >> 2, c = rem & 3;
        uint32_t dst = sbase + (uint32_t)op * 8192u + (uint32_t)(r * 64) + (uint32_t)((c ^ ((r >> 1) & 3)) * 16);
        const __nv_bfloat16* src;
        if (op == 0)      src = g_xh + (size_t)(m0 + r) * DIM + k0 + c * 8;
        else if (op == 1) src = g_xl + (size_t)(m0 + r) * DIM + k0 + c * 8;
        else if (op == 2) src = g_wh + (size_t)(n0 + r) * DIM + k0 + c * 8;
        else              src = g_wl + (size_t)(n0 + r) * DIM + k0 + c * 8;
        cp16(dst, src);
    }
}

__global__ void __launch_bounds__(256, 2) out_gemm_mma(float* __restrict__ out) {
    extern __shared__ __align__(16) char dsm[];
    const uint32_t sb = smem_u32(dsm);
    float* sbias = (float*)(dsm + 3 * OSTG);
    const int tid = threadIdx.x, lane = tid & 31, wid = tid >> 5;
    const int n0 = blockIdx.x * 128, m0 = blockIdx.y * 128;
    const int wm = wid & 1, wn = wid >> 1;

    if (tid < 128) sbias[tid] = g_beff[n0 + tid];

    float c[4][4][4];
    #pragma unroll
    for (int mf = 0; mf < 4; mf++)
        #pragma unroll
        for (int nf = 0; nf < 4; nf++)
            #pragma unroll
            for (int r = 0; r < 4; r++) c[mf][nf][r] = 0.0f;

    load_stage_out(sb,        m0, n0, 0,  tid); cp_commit();
    load_stage_out(sb + OSTG, m0, n0, 32, tid); cp_commit();

    const int a_row  = wm * 64 + (lane & 15);
    const int a_kc   = (lane >> 4) & 1;
    const int b_row4 = wn * 32 + (lane & 7) + ((lane >> 4) << 3);
    const int b_kpar = (lane >> 3) & 1;

    int cs = 0, ls = 2;
    for (int it = 0; it < 64; it++) {
        cp_wait1();
        __syncthreads();
        int pf = it + 2; if (pf > 63) pf = 63;
        load_stage_out(sb + (uint32_t)ls * OSTG, m0, n0, pf * 32, tid);
        cp_commit();
        const uint32_t sa = sb + (uint32_t)cs * OSTG;

        #pragma unroll
        for (int s2 = 0; s2 < 2; s2++) {
            uint32_t ah[4][4], al[4][4];
            #pragma unroll
            for (int mf = 0; mf < 4; mf++) {
                int r = a_row + mf * 16;
                uint32_t addr = sa + (uint32_t)(r * 64) +
                                (uint32_t)((((s2 << 1) | a_kc) ^ ((r >> 1) & 3)) * 16);
                ldsm4(ah[mf][0], ah[mf][1], ah[mf][2], ah[mf][3], addr);
                ldsm4(al[mf][0], al[mf][1], al[mf][2], al[mf][3], addr + 8192u);
            }
            #pragma unroll
            for (int np = 0; np < 2; np++) {
                int r = b_row4 + np * 16;
                uint32_t base = (uint32_t)(r * 64) +
                                (uint32_t)((((s2 << 1) | b_kpar) ^ ((r >> 1) & 3)) * 16);
                uint32_t bh0, bh1, bh2, bh3, bl0, bl1, bl2, bl3;
                ldsm4(bh0, bh1, bh2, bh3, sa + 16384u + base);
                ldsm4(bl0, bl1, bl2, bl3, sa + 24576u + base);
                #pragma unroll
                for (int mf = 0; mf < 4; mf++) {
                    mma16816bf(c[mf][2 * np],     ah[mf], bh0, bh1);
                    mma16816bf(c[mf][2 * np],     ah[mf], bl0, bl1);
                    mma16816bf(c[mf][2 * np],     al[mf], bh0, bh1);
                    mma16816bf(c[mf][2 * np + 1], ah[mf], bh2, bh3);
                    mma16816bf(c[mf][2 * np + 1], ah[mf], bl2, bl3);
                    mma16816bf(c[mf][2 * np + 1], al[mf], bh2, bh3);
                }
            }
        }
        cs = (cs == 2) ? 0 : cs + 1;
        ls = (ls == 2) ? 0 : ls + 1;
    }
    cp_wait0();

    #pragma unroll
    for (int mf = 0; mf < 4; mf++) {
        int r0 = m0 + wm * 64 + mf * 16 + (lane >> 2);
        #pragma unroll
        for (int nf = 0; nf < 4; nf++) {
            int cb = wn * 32 + nf * 8 + (lane & 3) * 2;
            float2 v0, v1;
            v0.x = c[mf][nf][0] + sbias[cb];
            v0.y = c[mf][nf][1] + sbias[cb + 1];
            v1.x = c[mf][nf][2] + sbias[cb];
            v1.y = c[mf][nf][3] + sbias[cb + 1];
            *(float2*)&out[(size_t)r0 * DIM + n0 + cb] = v0;
            *(float2*)&out[(size_t)(r0 + 8) * DIM + n0 + cb] = v1;
        }
    }
}

// ---------------- host orchestration ----------------
extern "C" void kernel_launch(void* const* d_in, const int* in_sizes, int n_in,
                              void* d_out, int out_size) {
    const float* x      = (const float*)d_in[0];
    const float* weight = (const float*)d_in[1];
    const float* bias   = (const float*)d_in[2];
    float* out          = (float*)d_out;

    cudaFuncSetAttribute(gram_mma,     cudaFuncAttributeMaxDynamicSharedMemorySize, 3 * OSTG);
    cudaFuncSetAttribute(out_gemm_mma, cudaFuncAttributeMaxDynamicSharedMemorySize, 3 * OSTG + 512);

    zero_kernel<<<1026, 256>>>();
    split_x_mean_kernel<<<256, 512>>>(x);
    mean_scale_kernel<<<1, 512>>>();
    gram_mma<<<dim3(10, 64), 256, 3 * OSTG>>>(0);
    cov_kernel<<<1024, 256>>>();
    scalars_kernel<<<1, 1>>>();
    init_yz_kernel<<<1024, 256>>>();

    int cur = 0;
    for (int it = 0; it < NITER; it++) {
        ns_T_kernel<<<dim3(8, 8), 256>>>(cur);
        ns_pair_kernel<<<dim3(8, 8, 2), 256>>>(cur);
        cur ^= 1;
    }

    fold_kernel<<<dim3(4, 64), 256>>>(weight, cur);
    bias_kernel<<<DIM, 256>>>(bias);
    split_w_kernel<<<4096, 256>>>();

    out_gemm_mma<<<dim3(16, 256), 256, 3 * OSTG + 512>>>(out);
}

// round 17
// speedup vs baseline: 1.2119x; 1.0218x over previous
#include <cuda_runtime.h>
#include <cuda_bf16.h>
#include <math.h>
#include <stdint.h>

// Problem constants
#define NROWS 32768
#define DIM   2048
#define BLK   512
#define NX    (NROWS * DIM / BLK)   // 131072 rows of X
#define EPSV  1e-5f
#define NITER 5

// ---------------- device scratch (no allocations allowed) ----------------
__device__ float g_meanAcc[BLK];
__device__ float g_mean[BLK];
__device__ float g_G[BLK * BLK];
__device__ float g_C[BLK * BLK];
__device__ float g_Y[2][BLK * BLK];
__device__ float g_Z[2][BLK * BLK];
__device__ float g_T[BLK * BLK];
__device__ float g_normSq;
__device__ float g_invNorm;
__device__ float g_zscale;
__device__ float g_Wf[DIM * DIM];      // folded weight fp32 (for bias)
__device__ float g_beff[DIM];

// bf16 hi/lo splits
__device__ __nv_bfloat16 g_xh[(size_t)NROWS * DIM];   // x row-major hi
__device__ __nv_bfloat16 g_xl[(size_t)NROWS * DIM];   // x row-major lo
__device__ __nv_bfloat16 g_wh[(size_t)DIM * DIM];     // folded weight hi
__device__ __nv_bfloat16 g_wl[(size_t)DIM * DIM];     // folded weight lo
__device__ __nv_bfloat16 g_vh[(size_t)DIM * DIM];     // raw weight hi
__device__ __nv_bfloat16 g_vl[(size_t)DIM * DIM];     // raw weight lo
__device__ __nv_bfloat16 g_zth[BLK * BLK];            // Zfinal^T hi [512][512] (n-major)
__device__ __nv_bfloat16 g_ztl[BLK * BLK];            // Zfinal^T lo

// symmetric gram tile pairs (lower triangle, 10 of 16)
__constant__ int c_pa[10] = {0,1,1,2,2,2,3,3,3,3};
__constant__ int c_pb[10] = {0,0,1,0,1,2,0,1,2,3};

// ---------------- PTX helpers (sm_80+ features only) ----------------
__device__ __forceinline__ uint32_t smem_u32(const void* p) {
    uint32_t a;
    asm("{ .reg .u64 t; cvta.to.shared.u64 t, %1; cvt.u32.u64 %0, t; }" : "=r"(a) : "l"(p));
    return a;
}
__device__ __forceinline__ void cp16(uint32_t d, const void* s) {
    asm volatile("cp.async.cg.shared.global [%0], [%1], 16;" :: "r"(d), "l"(s));
}
__device__ __forceinline__ void cp_commit() { asm volatile("cp.async.commit_group;"); }
__device__ __forceinline__ void cp_wait0()  { asm volatile("cp.async.wait_group 0;"); }
__device__ __forceinline__ void cp_wait1()  { asm volatile("cp.async.wait_group 1;"); }

__device__ __forceinline__ void ldsm4(uint32_t& r0, uint32_t& r1, uint32_t& r2, uint32_t& r3, uint32_t a) {
    asm volatile("ldmatrix.sync.aligned.m8n8.x4.shared.b16 {%0,%1,%2,%3}, [%4];"
                 : "=r"(r0), "=r"(r1), "=r"(r2), "=r"(r3) : "r"(a));
}
__device__ __forceinline__ void ldsm4t(uint32_t& r0, uint32_t& r1, uint32_t& r2, uint32_t& r3, uint32_t a) {
    asm volatile("ldmatrix.sync.aligned.m8n8.x4.trans.shared.b16 {%0,%1,%2,%3}, [%4];"
                 : "=r"(r0), "=r"(r1), "=r"(r2), "=r"(r3) : "r"(a));
}
__device__ __forceinline__ void mma16816bf(float* c, const uint32_t* a, uint32_t b0, uint32_t b1) {
    asm volatile("mma.sync.aligned.m16n8k16.row.col.f32.bf16.bf16.f32 "
                 "{%0,%1,%2,%3}, {%4,%5,%6,%7}, {%8,%9}, {%0,%1,%2,%3};"
                 : "+f"(c[0]), "+f"(c[1]), "+f"(c[2]), "+f"(c[3])
                 : "r"(a[0]), "r"(a[1]), "r"(a[2]), "r"(a[3]), "r"(b0), "r"(b1));
}

// ---------------- zero accumulators ----------------
__global__ void zero_kernel() {
    int idx = blockIdx.x * blockDim.x + threadIdx.x;
    int total = BLK * BLK + BLK + 1;
    for (int i = idx; i < total; i += gridDim.x * blockDim.x) {
        if (i < BLK * BLK) g_G[i] = 0.0f;
        else if (i < BLK * BLK + BLK) g_meanAcc[i - BLK * BLK] = 0.0f;
        else g_normSq = 0.0f;
    }
}

// ---------------- fused: bf16 hi/lo split of x (row-major) + column sums ----------------
__global__ void __launch_bounds__(512) split_x_mean_kernel(const float* __restrict__ x) {
    const int t = threadIdx.x;
    const size_t base = (size_t)blockIdx.x * 512 * BLK;
    float s = 0.0f;
    #pragma unroll 4
    for (int r = 0; r < 512; r++) {
        size_t idx = base + (size_t)r * BLK + t;
        float v = x[idx];
        __nv_bfloat16 h = __float2bfloat16(v);
        __nv_bfloat16 l = __float2bfloat16(v - __bfloat162float(h));
        g_xh[idx] = h;
        g_xl[idx] = l;
        s += v;
    }
    atomicAdd(&g_meanAcc[t], s);
}

// ---------------- raw weight bf16 hi/lo split ----------------
__global__ void split_v_kernel(const float* __restrict__ W) {
    size_t i = ((size_t)blockIdx.x * 256 + threadIdx.x) * 4;
    float4 v = *(const float4*)(W + i);
    __nv_bfloat16 h0 = __float2bfloat16(v.x), h1 = __float2bfloat16(v.y);
    __nv_bfloat16 h2 = __float2bfloat16(v.z), h3 = __float2bfloat16(v.w);
    __nv_bfloat16 l0 = __float2bfloat16(v.x - __bfloat162float(h0));
    __nv_bfloat16 l1 = __float2bfloat16(v.y - __bfloat162float(h1));
    __nv_bfloat16 l2 = __float2bfloat16(v.z - __bfloat162float(h2));
    __nv_bfloat16 l3 = __float2bfloat16(v.w - __bfloat162float(h3));
    *(__nv_bfloat162*)(g_vh + i)     = __halves2bfloat162(h0, h1);
    *(__nv_bfloat162*)(g_vh + i + 2) = __halves2bfloat162(h2, h3);
    *(__nv_bfloat162*)(g_vl + i)     = __halves2bfloat162(l0, l1);
    *(__nv_bfloat162*)(g_vl + i + 2) = __halves2bfloat162(l2, l3);
}

__global__ void mean_scale_kernel() {
    int t = threadIdx.x;
    g_mean[t] = g_meanAcc[t] * (1.0f / (float)NX);
}

// ============ MMA tile machinery ============
#define OSTG 32768

// ---------------- gram via mma bf16x3 with ldmatrix.trans (reads row-major splits) ----------------
__device__ __forceinline__ void load_stage_gram(uint32_t sbase, int a0, int b0, int k0, int tid) {
    #pragma unroll
    for (int i = 0; i < 8; i++) {
        int q = tid + i * 256;
        int op = q >> 9, rem = q & 511;
        int r = rem >> 4;          // k-row 0..31
        int c = rem & 15;          // 16B chunk 0..15 (col dim)
        uint32_t dst = sbase + (uint32_t)op * 8192u + (uint32_t)(r * 256) + (uint32_t)((c ^ (r & 7)) * 16);
        int col = ((op < 2) ? a0 : b0) + c * 8;
        const __nv_bfloat16* buf = (op & 1) ? g_xl : g_xh;
        cp16(dst, buf + (size_t)(k0 + r) * BLK + col);
    }
}

__global__ void __launch_bounds__(256, 2) gram_mma(int dummy) {
    extern __shared__ __align__(16) char dsm[];
    const uint32_t sb = smem_u32(dsm);
    const int tid = threadIdx.x, lane = tid & 31, wid = tid >> 5;
    const int a0 = c_pa[blockIdx.x] * 128;
    const int b0 = c_pb[blockIdx.x] * 128;
    const int kbase = blockIdx.y * 2048;
    const int wm = wid & 1, wn = wid >> 1;

    float c[4][4][4];
    #pragma unroll
    for (int mf = 0; mf < 4; mf++)
        #pragma unroll
        for (int nf = 0; nf < 4; nf++)
            #pragma unroll
            for (int r = 0; r < 4; r++) c[mf][nf][r] = 0.0f;

    load_stage_gram(sb,        a0, b0, kbase,      tid); cp_commit();
    load_stage_gram(sb + OSTG, a0, b0, kbase + 32, tid); cp_commit();

    const int a_k    = (lane & 7) + ((lane >> 4) << 3);
    const int a_moff = ((lane >> 3) & 1) * 8;
    const int b_k    = (lane & 7) + (((lane >> 3) & 1) << 3);
    const int b_noff = ((lane >> 4) & 1) * 8;

    int cs = 0, ls = 2;
    for (int it = 0; it < 64; it++) {
        cp_wait1();
        __syncthreads();
        int pf = it + 2; if (pf > 63) pf = 63;
        load_stage_gram(sb + (uint32_t)ls * OSTG, a0, b0, kbase + pf * 32, tid);
        cp_commit();
        const uint32_t sa = sb + (uint32_t)cs * OSTG;

        #pragma unroll
        for (int s2 = 0; s2 < 2; s2++) {
            const int ak = a_k + s2 * 16;
            const int bk = b_k + s2 * 16;
            uint32_t ah[4][4], al[4][4];
            #pragma unroll
            for (int mf = 0; mf < 4; mf++) {
                int m_local = wm * 64 + mf * 16 + a_moff;
                int chunk = m_local >> 3;
                uint32_t addr = sa + (uint32_t)(ak * 256) + (uint32_t)((chunk ^ (ak & 7)) * 16);
                ldsm4t(ah[mf][0], ah[mf][1], ah[mf][2], ah[mf][3], addr);
                ldsm4t(al[mf][0], al[mf][1], al[mf][2], al[mf][3], addr + 8192u);
            }
            #pragma unroll
            for (int np = 0; np < 2; np++) {
                int n_local = wn * 32 + np * 16 + b_noff;
                int chunk = n_local >> 3;
                uint32_t addr = sa + 16384u + (uint32_t)(bk * 256) + (uint32_t)((chunk ^ (bk & 7)) * 16);
                uint32_t bh0, bh1, bh2, bh3, bl0, bl1, bl2, bl3;
                ldsm4t(bh0, bh1, bh2, bh3, addr);
                ldsm4t(bl0, bl1, bl2, bl3, addr + 8192u);
                #pragma unroll
                for (int mf = 0; mf < 4; mf++) {
                    mma16816bf(c[mf][2 * np],     ah[mf], bh0, bh1);
                    mma16816bf(c[mf][2 * np],     ah[mf], bl0, bl1);
                    mma16816bf(c[mf][2 * np],     al[mf], bh0, bh1);
                    mma16816bf(c[mf][2 * np + 1], ah[mf], bh2, bh3);
                    mma16816bf(c[mf][2 * np + 1], ah[mf], bl2, bl3);
                    mma16816bf(c[mf][2 * np + 1], al[mf], bh2, bh3);
                }
            }
        }
        cs = (cs == 2) ? 0 : cs + 1;
        ls = (ls == 2) ? 0 : ls + 1;
    }
    cp_wait0();

    #pragma unroll
    for (int mf = 0; mf < 4; mf++) {
        int r0 = a0 + wm * 64 + mf * 16 + (lane >> 2);
        #pragma unroll
        for (int nf = 0; nf < 4; nf++) {
            int cb = b0 + wn * 32 + nf * 8 + (lane & 3) * 2;
            atomicAdd(&g_G[r0 * BLK + cb],           c[mf][nf][0]);
            atomicAdd(&g_G[r0 * BLK + cb + 1],       c[mf][nf][1]);
            atomicAdd(&g_G[(r0 + 8) * BLK + cb],     c[mf][nf][2]);
            atomicAdd(&g_G[(r0 + 8) * BLK + cb + 1], c[mf][nf][3]);
        }
    }
}

// ---------------- cov = G/n - m m^T + eps I (mirror upper from lower) ----------------
__global__ void cov_kernel() {
    int idx = blockIdx.x * blockDim.x + threadIdx.x;
    int a = idx >> 9, b = idx & 511;
    float graw = (a >= b) ? g_G[a * BLK + b] : g_G[b * BLK + a];
    float c = graw * (1.0f / (float)NX) - g_mean[a] * g_mean[b] + (a == b ? EPSV : 0.0f);
    g_C[idx] = c;
    float v = c * c;
    #pragma unroll
    for (int o = 16; o > 0; o >>= 1) v += __shfl_xor_sync(0xffffffffu, v, o);
    __shared__ float ws[8];
    int lane = threadIdx.x & 31, w = threadIdx.x >> 5;
    if (lane == 0) ws[w] = v;
    __syncthreads();
    if (w == 0) {
        float t = (lane < 8) ? ws[lane] : 0.0f;
        #pragma unroll
        for (int o = 4; o > 0; o >>= 1) t += __shfl_xor_sync(0xffffffffu, t, o);
        if (lane == 0) atomicAdd(&g_normSq, t);
    }
}

__global__ void scalars_kernel() {
    float norm = sqrtf(g_normSq);
    g_invNorm = 1.0f / norm;
    g_zscale = rsqrtf(norm);
}

__global__ void init_yz_kernel() {
    int idx = blockIdx.x * blockDim.x + threadIdx.x;
    int a = idx >> 9, b = idx & 511;
    g_Y[0][idx] = g_C[idx] * g_invNorm;
    g_Z[0][idx] = (a == b) ? 1.0f : 0.0f;
}

// ---------------- 512x512x512 GEMM core (SIMT, 64x64 tile) ----------------
__device__ __forceinline__ void mm512_tile(const float* __restrict__ A,
                                           const float* __restrict__ B,
                                           int m0, int n0, float acc[4][4]) {
    __shared__ float As[16][68];
    __shared__ float Bs[16][68];
    const int tid = threadIdx.x;
    const int tx = tid & 15, ty = tid >> 4;
    for (int k0 = 0; k0 < 512; k0 += 16) {
        #pragma unroll
        for (int i = 0; i < 4; i++) {
            int l = tid + i * 256;
            int m = l >> 4, k = l & 15;
            As[k][m] = A[(m0 + m) * 512 + k0 + k];
            int kb = l >> 6, n = l & 63;
            Bs[kb][n] = B[(k0 + kb) * 512 + n0 + n];
        }
        __syncthreads();
        #pragma unroll
        for (int k = 0; k < 16; k++) {
            float a[4], b[4];
            *(float4*)a = *(const float4*)&As[k][ty * 4];
            *(float4*)b = *(const float4*)&Bs[k][tx * 4];
            #pragma unroll
            for (int i = 0; i < 4; i++)
                #pragma unroll
                for (int j = 0; j < 4; j++) acc[i][j] += a[i] * b[j];
        }
        __syncthreads();
    }
}

__global__ void __launch_bounds__(256) ns_T_kernel(int cur) {
    const float* A = g_Z[cur];
    const float* B = g_Y[cur];
    int m0 = blockIdx.y * 64, n0 = blockIdx.x * 64;
    float acc[4][4] = {};
    mm512_tile(A, B, m0, n0, acc);
    int tx = threadIdx.x & 15, ty = threadIdx.x >> 4;
    #pragma unroll
    for (int i = 0; i < 4; i++)
        #pragma unroll
        for (int j = 0; j < 4; j++) {
            int r = m0 + ty * 4 + i, c = n0 + tx * 4 + j;
            g_T[r * 512 + c] = (r == c ? 1.5f : 0.0f) - 0.5f * acc[i][j];
        }
}

__global__ void __launch_bounds__(256) ns_pair_kernel(int cur) {
    const float* A; const float* B; float* C;
    if (blockIdx.z == 0) { A = g_Y[cur]; B = g_T; C = g_Y[cur ^ 1]; }
    else                 { A = g_T; B = g_Z[cur]; C = g_Z[cur ^ 1]; }
    int m0 = blockIdx.y * 64, n0 = blockIdx.x * 64;
    float acc[4][4] = {};
    mm512_tile(A, B, m0, n0, acc);
    int tx = threadIdx.x & 15, ty = threadIdx.x >> 4;
    #pragma unroll
    for (int i = 0; i < 4; i++)
        #pragma unroll
        for (int j = 0; j < 4; j++)
            C[(m0 + ty * 4 + i) * 512 + n0 + tx * 4 + j] = acc[i][j];
}

// ---------------- transpose-split Zfinal for fold_mma ----------------
__global__ void zt_split_kernel(int zfin) {
    const float* Zf = g_Z[zfin];
    int i = blockIdx.x * 256 + threadIdx.x;      // 1024 blocks
    int n = i >> 9, k = i & 511;
    float v = Zf[k * 512 + n];
    __nv_bfloat16 h = __float2bfloat16(v);
    g_zth[i] = h;
    g_ztl[i] = __float2bfloat16(v - __bfloat162float(h));
}

// ---------------- fold via mma bf16x3: Wf = (W8192x512 @ Zf) * zscale ----------------
// BK=32, 64B-row 4-chunk XOR swizzle (matches out_gemm's stage format)
__device__ __forceinline__ void load_stage_fold(uint32_t sbase, int m0, int n0, int k0, int tid) {
    #pragma unroll
    for (int i = 0; i < 8; i++) {
        int q = tid + i * 256;
        int op = q >> 9, rem = q & 511;
        int r = rem >> 2, c = rem & 3;
        uint32_t dst = sbase + (uint32_t)op * 8192u + (uint32_t)(r * 64) + (uint32_t)((c ^ ((r >> 1) & 3)) * 16);
        const __nv_bfloat16* src;
        if (op == 0)      src = g_vh  + (size_t)(m0 + r) * 512 + k0 + c * 8;
        else if (op == 1) src = g_vl  + (size_t)(m0 + r) * 512 + k0 + c * 8;
        else if (op == 2) src = g_zth + (size_t)(n0 + r) * 512 + k0 + c * 8;
        else              src = g_ztl + (size_t)(n0 + r) * 512 + k0 + c * 8;
        cp16(dst, src);
    }
}

__global__ void __launch_bounds__(256) fold_mma(int dummy) {
    extern __shared__ __align__(16) char dsm[];
    const uint32_t sb = smem_u32(dsm);
    const int tid = threadIdx.x, lane = tid & 31, wid = tid >> 5;
    const int n0 = blockIdx.x * 128;   // N = 512 -> 4
    const int m0 = blockIdx.y * 128;   // M = 8192 -> 64
    const int wm = wid & 1, wn = wid >> 1;

    float c[4][4][4];
    #pragma unroll
    for (int mf = 0; mf < 4; mf++)
        #pragma unroll
        for (int nf = 0; nf < 4; nf++)
            #pragma unroll
            for (int r = 0; r < 4; r++) c[mf][nf][r] = 0.0f;

    load_stage_fold(sb,        m0, n0, 0,  tid); cp_commit();
    load_stage_fold(sb + OSTG, m0, n0, 32, tid); cp_commit();

    const int a_row  = wm * 64 + (lane & 15);
    const int a_kc   = (lane >> 4) & 1;
    const int b_row4 = wn * 32 + (lane & 7) + ((lane >> 4) << 3);
    const int b_kpar = (lane >> 3) & 1;

    int cs = 0, ls = 2;
    for (int it = 0; it < 16; it++) {            // K = 512, BK = 32
        cp_wait1();
        __syncthreads();
        int pf = it + 2; if (pf > 15) pf = 15;
        load_stage_fold(sb + (uint32_t)ls * OSTG, m0, n0, pf * 32, tid);
        cp_commit();
        const uint32_t sa = sb + (uint32_t)cs * OSTG;

        #pragma unroll
        for (int s2 = 0; s2 < 2; s2++) {
            uint32_t ah[4][4], al[4][4];
            #pragma unroll
            for (int mf = 0; mf < 4; mf++) {
                int r = a_row + mf * 16;
                uint32_t addr = sa + (uint32_t)(r * 64) +
                                (uint32_t)((((s2 << 1) | a_kc) ^ ((r >> 1) & 3)) * 16);
                ldsm4(ah[mf][0], ah[mf][1], ah[mf][2], ah[mf][3], addr);
                ldsm4(al[mf][0], al[mf][1], al[mf][2], al[mf][3], addr + 8192u);
            }
            #pragma unroll
            for (int np = 0; np < 2; np++) {
                int r = b_row4 + np * 16;
                uint32_t base = (uint32_t)(r * 64) +
                                (uint32_t)((((s2 << 1) | b_kpar) ^ ((r >> 1) & 3)) * 16);
                uint32_t bh0, bh1, bh2, bh3, bl0, bl1, bl2, bl3;
                ldsm4(bh0, bh1, bh2, bh3, sa + 16384u + base);
                ldsm4(bl0, bl1, bl2, bl3, sa + 24576u + base);
                #pragma unroll
                for (int mf = 0; mf < 4; mf++) {
                    mma16816bf(c[mf][2 * np],     ah[mf], bh0, bh1);
                    mma16816bf(c[mf][2 * np],     ah[mf], bl0, bl1);
                    mma16816bf(c[mf][2 * np],     al[mf], bh0, bh1);
                    mma16816bf(c[mf][2 * np + 1], ah[mf], bh2, bh3);
                    mma16816bf(c[mf][2 * np + 1], ah[mf], bl2, bl3);
                    mma16816bf(c[mf][2 * np + 1], al[mf], bh2, bh3);
                }
            }
        }
        cs = (cs == 2) ? 0 : cs + 1;
        ls = (ls == 2) ? 0 : ls + 1;
    }
    cp_wait0();

    // epilogue: scale, write fp32 Wf AND bf16 hi/lo split (deletes split_w)
    float sc = g_zscale;
    #pragma unroll
    for (int mf = 0; mf < 4; mf++) {
        int r0 = m0 + wm * 64 + mf * 16 + (lane >> 2);
        #pragma unroll
        for (int nf = 0; nf < 4; nf++) {
            int cb = n0 + wn * 32 + nf * 8 + (lane & 3) * 2;
            #pragma unroll
            for (int half = 0; half < 2; half++) {
                int row = r0 + half * 8;
                float w0 = c[mf][nf][half * 2 + 0] * sc;
                float w1 = c[mf][nf][half * 2 + 1] * sc;
                size_t idx = (size_t)row * 512 + cb;
                *(float2*)&g_Wf[idx] = make_float2(w0, w1);
                __nv_bfloat16 h0 = __float2bfloat16(w0), h1 = __float2bfloat16(w1);
                __nv_bfloat16 l0 = __float2bfloat16(w0 - __bfloat162float(h0));
                __nv_bfloat16 l1 = __float2bfloat16(w1 - __bfloat162float(h1));
                *(__nv_bfloat162*)(g_wh + idx) = __halves2bfloat162(h0, h1);
                *(__nv_bfloat162*)(g_wl + idx) = __halves2bfloat162(l0, l1);
            }
        }
    }
}

// ---------------- b_eff ----------------
__global__ void bias_kernel(const float* __restrict__ bias) {
    int o = blockIdx.x;
    int t = threadIdx.x;
    float s = 0.0f;
    for (int k = t; k < DIM; k += 256)
        s += g_Wf[o * DIM + k] * g_mean[k & 511];
    #pragma unroll
    for (int off = 16; off > 0; off >>= 1) s += __shfl_xor_sync(0xffffffffu, s, off);
    __shared__ float ws[8];
    int lane = t & 31, w = t >> 5;
    if (lane == 0) ws[w] = s;
    __syncthreads();
    if (t == 0) {
        float tot = 0.0f;
        #pragma unroll
        for (int i = 0; i < 8; i++) tot += ws[i];
        g_beff[o] = bias[o] - tot;
    }
}

// ---------------- main GEMM via mma bf16x3 (3-stage, BK=32, 2 CTAs/SM) ----------------
__device__ __forceinline__ void load_stage_out(uint32_t sbase, int m0, int n0, int k0, int tid) {
    #pragma unroll
    for (int i = 0; i < 8; i++) {
        int q = tid + i * 256;
        int op = q >> 9, rem = q & 511;
        int r = rem >> 2, c = rem & 3;
        uint32_t dst = sbase + (uint32_t)op * 8192u + (uint32_t)(r * 64) + (uint32_t)((c ^ ((r >> 1) & 3)) * 16);
        const __nv_bfloat16* src;
        if (op == 0)      src = g_xh + (size_t)(m0 + r) * DIM + k0 + c * 8;
        else if (op == 1) src = g_xl + (size_t)(m0 + r) * DIM + k0 + c * 8;
        else if (op == 2) src = g_wh + (size_t)(n0 + r) * DIM + k0 + c * 8;
        else              src = g_wl + (size_t)(n0 + r) * DIM + k0 + c * 8;
        cp16(dst, src);
    }
}

__global__ void __launch_bounds__(256, 2) out_gemm_mma(float* __restrict__ out) {
    extern __shared__ __align__(16) char dsm[];
    const uint32_t sb = smem_u32(dsm);
    float* sbias = (float*)(dsm + 3 * OSTG);
    const int tid = threadIdx.x, lane = tid & 31, wid = tid >> 5;
    const int n0 = blockIdx.x * 128, m0 = blockIdx.y * 128;
    const int wm = wid & 1, wn = wid >> 1;

    if (tid < 128) sbias[tid] = g_beff[n0 + tid];

    float c[4][4][4];
    #pragma unroll
    for (int mf = 0; mf < 4; mf++)
        #pragma unroll
        for (int nf = 0; nf < 4; nf++)
            #pragma unroll
            for (int r = 0; r < 4; r++) c[mf][nf][r] = 0.0f;

    load_stage_out(sb,        m0, n0, 0,  tid); cp_commit();
    load_stage_out(sb + OSTG, m0, n0, 32, tid); cp_commit();

    const int a_row  = wm * 64 + (lane & 15);
    const int a_kc   = (lane >> 4) & 1;
    const int b_row4 = wn * 32 + (lane & 7) + ((lane >> 4) << 3);
    const int b_kpar = (lane >> 3) & 1;

    int cs = 0, ls = 2;
    for (int it = 0; it < 64; it++) {
        cp_wait1();
        __syncthreads();
        int pf = it + 2; if (pf > 63) pf = 63;
        load_stage_out(sb + (uint32_t)ls * OSTG, m0, n0, pf * 32, tid);
        cp_commit();
        const uint32_t sa = sb + (uint32_t)cs * OSTG;

        #pragma unroll
        for (int s2 = 0; s2 < 2; s2++) {
            uint32_t ah[4][4], al[4][4];
            #pragma unroll
            for (int mf = 0; mf < 4; mf++) {
                int r = a_row + mf * 16;
                uint32_t addr = sa + (uint32_t)(r * 64) +
                                (uint32_t)((((s2 << 1) | a_kc) ^ ((r >> 1) & 3)) * 16);
                ldsm4(ah[mf][0], ah[mf][1], ah[mf][2], ah[mf][3], addr);
                ldsm4(al[mf][0], al[mf][1], al[mf][2], al[mf][3], addr + 8192u);
            }
            #pragma unroll
            for (int np = 0; np < 2; np++) {
                int r = b_row4 + np * 16;
                uint32_t base = (uint32_t)(r * 64) +
                                (uint32_t)((((s2 << 1) | b_kpar) ^ ((r >> 1) & 3)) * 16);
                uint32_t bh0, bh1, bh2, bh3, bl0, bl1, bl2, bl3;
                ldsm4(bh0, bh1, bh2, bh3, sa + 16384u + base);
                ldsm4(bl0, bl1, bl2, bl3, sa + 24576u + base);
                #pragma unroll
                for (int mf = 0; mf < 4; mf++) {
                    mma16816bf(c[mf][2 * np],     ah[mf], bh0, bh1);
                    mma16816bf(c[mf][2 * np],     ah[mf], bl0, bl1);
                    mma16816bf(c[mf][2 * np],     al[mf], bh0, bh1);
                    mma16816bf(c[mf][2 * np + 1], ah[mf], bh2, bh3);
                    mma16816bf(c[mf][2 * np + 1], ah[mf], bl2, bl3);
                    mma16816bf(c[mf][2 * np + 1], al[mf], bh2, bh3);
                }
            }
        }
        cs = (cs == 2) ? 0 : cs + 1;
        ls = (ls == 2) ? 0 : ls + 1;
    }
    cp_wait0();

    #pragma unroll
    for (int mf = 0; mf < 4; mf++) {
        int r0 = m0 + wm * 64 + mf * 16 + (lane >> 2);
        #pragma unroll
        for (int nf = 0; nf < 4; nf++) {
            int cb = wn * 32 + nf * 8 + (lane & 3) * 2;
            float2 v0, v1;
            v0.x = c[mf][nf][0] + sbias[cb];
            v0.y = c[mf][nf][1] + sbias[cb + 1];
            v1.x = c[mf][nf][2] + sbias[cb];
            v1.y = c[mf][nf][3] + sbias[cb + 1];
            *(float2*)&out[(size_t)r0 * DIM + n0 + cb] = v0;
            *(float2*)&out[(size_t)(r0 + 8) * DIM + n0 + cb] = v1;
        }
    }
}

// ---------------- host orchestration ----------------
extern "C" void kernel_launch(void* const* d_in, const int* in_sizes, int n_in,
                              void* d_out, int out_size) {
    const float* x      = (const float*)d_in[0];
    const float* weight = (const float*)d_in[1];
    const float* bias   = (const float*)d_in[2];
    float* out          = (float*)d_out;

    cudaFuncSetAttribute(gram_mma,     cudaFuncAttributeMaxDynamicSharedMemorySize, 3 * OSTG);
    cudaFuncSetAttribute(fold_mma,     cudaFuncAttributeMaxDynamicSharedMemorySize, 3 * OSTG);
    cudaFuncSetAttribute(out_gemm_mma, cudaFuncAttributeMaxDynamicSharedMemorySize, 3 * OSTG + 512);

    zero_kernel<<<1026, 256>>>();
    split_x_mean_kernel<<<256, 512>>>(x);
    mean_scale_kernel<<<1, 512>>>();
    split_v_kernel<<<4096, 256>>>(weight);
    gram_mma<<<dim3(10, 64), 256, 3 * OSTG>>>(0);
    cov_kernel<<<1024, 256>>>();
    scalars_kernel<<<1, 1>>>();
    init_yz_kernel<<<1024, 256>>>();

    int cur = 0;
    for (int it = 0; it < NITER; it++) {
        ns_T_kernel<<<dim3(8, 8), 256>>>(cur);
        ns_pair_kernel<<<dim3(8, 8, 2), 256>>>(cur);
        cur ^= 1;
    }

    zt_split_kernel<<<1024, 256>>>(cur);
    fold_mma<<<dim3(4, 64), 256, 3 * OSTG>>>(0);
    bias_kernel<<<DIM, 256>>>(bias);
    out_gemm_mma<<<dim3(16, 256), 256, 3 * OSTG + 512>>>(out);
}